// round 7
// baseline (speedup 1.0000x reference)
#include <cuda_runtime.h>
#include <cuda_fp16.h>
#include <cuda_bf16.h>

#define DF 128
#define NMAX 50000
#define EMAX 800000
#define NCLS 10

// Scratch (allocation-free __device__ globals).
__device__ __align__(16) __half g_support[(size_t)NMAX * DF];   // fp16 gather source
__device__ __align__(16) float  g_h[(size_t)NMAX * DF];         // fp32 layer activations
__device__ __align__(16) int2   g_edge_s[EMAX];                 // sorted-by-dst (src, bits(w))
__device__ int g_cnt[NMAX + 1];
__device__ int g_rowptr[NMAX + 1];
__device__ int g_cur[NMAX + 1];
__device__ unsigned g_okey[3 * DF];

__device__ __forceinline__ unsigned fenc(float x) {
    unsigned u = __float_as_uint(x);
    return (u & 0x80000000u) ? ~u : (u | 0x80000000u);
}
__device__ __forceinline__ float fdec(unsigned k) {
    unsigned u = (k & 0x80000000u) ? (k & 0x7FFFFFFFu) : ~k;
    return __uint_as_float(u);
}
__device__ __forceinline__ unsigned smem_u32(const void* p) {
    return (unsigned)__cvta_generic_to_shared(p);
}

// ---------------- sort: counting sort of edges by dst -------------------

__global__ __launch_bounds__(256) void init_kernel(int N) {
    int i = blockIdx.x * 256 + threadIdx.x;
    if (i <= N) g_cnt[i] = 0;
    if (i < 3 * DF) g_okey[i] = 0u;
}

__global__ __launch_bounds__(256) void hist_kernel(const int* __restrict__ dst, int E) {
    int e = blockIdx.x * 256 + threadIdx.x;
    if (e < E) atomicAdd(&g_cnt[dst[e]], 1);
}

__global__ __launch_bounds__(1024) void scan_kernel(int N) {
    __shared__ int part[1024];
    __shared__ int carry[1024];
    int t = threadIdx.x;
    int chunk = (N + 1023) / 1024;
    int base = t * chunk;
    int s = 0;
    for (int j = 0; j < chunk; j++) {
        int idx = base + j;
        if (idx < N) s += g_cnt[idx];
    }
    part[t] = s;
    __syncthreads();
    for (int off = 1; off < 1024; off <<= 1) {
        int v = part[t];
        int add = (t >= off) ? part[t - off] : 0;
        __syncthreads();
        part[t] = v + add;
        __syncthreads();
    }
    carry[t] = (t == 0) ? 0 : part[t - 1];
    __syncthreads();
    int run = carry[t];
    for (int j = 0; j < chunk; j++) {
        int idx = base + j;
        if (idx < N) {
            g_rowptr[idx] = run;
            g_cur[idx] = run;
            run += g_cnt[idx];
        }
    }
    if (base < N && base + chunk >= N) g_rowptr[N] = run;
}

__global__ __launch_bounds__(256) void reorder_kernel(const int* __restrict__ src,
                                                      const int* __restrict__ dst,
                                                      const float* __restrict__ w,
                                                      int E) {
    int e = blockIdx.x * 256 + threadIdx.x;
    if (e >= E) return;
    int d = dst[e];
    int pos = atomicAdd(&g_cur[d], 1);
    g_edge_s[pos] = make_int2(src[e], __float_as_int(w[e]));
}

// ---------------- GEMM: support(fp16) = Ain(fp32) @ W, fp16 m16n8k16 mma ---

#define SH 136
#define GEMM_SMEM (2 * DF * SH * (int)sizeof(__half))  // 69632 B

__global__ __launch_bounds__(256, 2) void gemm_kernel(const float* __restrict__ A,
                                                      const float* __restrict__ W,
                                                      int N, int use_gh) {
    extern __shared__ __half smem_h[];
    __half* Ws = smem_h;             // [128 k][136 n]
    __half* As = smem_h + DF * SH;   // [128 m][136 k]
    const float* Ain = use_gh ? g_h : A;

    int t = threadIdx.x;
    int lane = t & 31;
    int wrp = t >> 5;
    int wm = wrp >> 1;
    int wn = wrp & 1;
    int r0 = blockIdx.x * 128;

    for (int i = t; i < DF * 32; i += 256) {
        int k = i >> 5;
        int n4 = (i & 31) * 4;
        float4 wv = *(const float4*)&W[k * DF + n4];
        __half2* dstp = (__half2*)&Ws[k * SH + n4];
        dstp[0] = __floats2half2_rn(wv.x, wv.y);
        dstp[1] = __floats2half2_rn(wv.z, wv.w);
    }
    for (int i = t; i < DF * 32; i += 256) {
        int row = i >> 5;
        int k4 = (i & 31) * 4;
        int gr = r0 + row;
        float4 av = make_float4(0.f, 0.f, 0.f, 0.f);
        if (gr < N) av = *(const float4*)&Ain[(size_t)gr * DF + k4];
        __half2* dstp = (__half2*)&As[row * SH + k4];
        dstp[0] = __floats2half2_rn(av.x, av.y);
        dstp[1] = __floats2half2_rn(av.z, av.w);
    }
    __syncthreads();

    float acc[2][8][4];
#pragma unroll
    for (int mt = 0; mt < 2; mt++)
#pragma unroll
        for (int nt = 0; nt < 8; nt++)
#pragma unroll
            for (int r = 0; r < 4; r++) acc[mt][nt][r] = 0.f;

    int gid = lane >> 2;
    int tig = lane & 3;

    int tr = lane & 7;
    int tile = lane >> 3;
    int row_off = (tile & 1) ? 8 : 0;
    int col_off = (tile & 2) ? 8 : 0;
    unsigned addrA[2];
#pragma unroll
    for (int mt = 0; mt < 2; mt++) {
        int m0 = wm * 32 + mt * 16;
        addrA[mt] = smem_u32(&As[(m0 + tr + row_off) * SH + col_off]);
    }
    unsigned addrB[4];
#pragma unroll
    for (int np = 0; np < 4; np++) {
        int nb = wn * 64 + np * 16;
        addrB[np] = smem_u32(&Ws[(tr + row_off) * SH + nb + col_off]);
    }

#pragma unroll
    for (int ks = 0; ks < 8; ks++) {
        unsigned af[2][4];
#pragma unroll
        for (int mt = 0; mt < 2; mt++) {
            asm volatile(
                "ldmatrix.sync.aligned.m8n8.x4.shared.b16 {%0,%1,%2,%3}, [%4];"
                : "=r"(af[mt][0]), "=r"(af[mt][1]), "=r"(af[mt][2]), "=r"(af[mt][3])
                : "r"(addrA[mt] + ks * 16 * (unsigned)sizeof(__half)));
        }
        unsigned bf[4][4];
#pragma unroll
        for (int np = 0; np < 4; np++) {
            asm volatile(
                "ldmatrix.sync.aligned.m8n8.x4.trans.shared.b16 {%0,%1,%2,%3}, [%4];"
                : "=r"(bf[np][0]), "=r"(bf[np][1]), "=r"(bf[np][2]), "=r"(bf[np][3])
                : "r"(addrB[np] + ks * 16 * SH * (unsigned)sizeof(__half)));
        }
#pragma unroll
        for (int np = 0; np < 4; np++) {
#pragma unroll
            for (int sub = 0; sub < 2; sub++) {
                int nt = np * 2 + sub;
#pragma unroll
                for (int mt = 0; mt < 2; mt++) {
                    asm volatile(
                        "mma.sync.aligned.m16n8k16.row.col.f32.f16.f16.f32 "
                        "{%0,%1,%2,%3}, {%4,%5,%6,%7}, {%8,%9}, {%0,%1,%2,%3};"
                        : "+f"(acc[mt][nt][0]), "+f"(acc[mt][nt][1]),
                          "+f"(acc[mt][nt][2]), "+f"(acc[mt][nt][3])
                        : "r"(af[mt][0]), "r"(af[mt][1]),
                          "r"(af[mt][2]), "r"(af[mt][3]),
                        "r"(bf[np][sub * 2]), "r"(bf[np][sub * 2 + 1]));
                }
            }
        }
    }

#pragma unroll
    for (int mt = 0; mt < 2; mt++) {
#pragma unroll
        for (int nt = 0; nt < 8; nt++) {
            int row = r0 + wm * 32 + mt * 16 + gid;
            int col = wn * 64 + nt * 8 + 2 * tig;
            if (row < N)
                *(__half2*)&g_support[(size_t)row * DF + col] =
                    __floats2half2_rn(acc[mt][nt][0], acc[mt][nt][1]);
            if (row + 8 < N)
                *(__half2*)&g_support[(size_t)(row + 8) * DF + col] =
                    __floats2half2_rn(acc[mt][nt][2], acc[mt][nt][3]);
        }
    }
}

// ---------------- segment-sum + bias (+relu, h write) + column max --------
// One warp per dst row; TWO edges per LDG.128 warp-instr (16 lanes x 16B
// each), 8 edges in flight; cross-half combine via shfl_xor(16).

__device__ __forceinline__ void fma8(float* a, const uint4 u, const float w) {
    float2 p0 = __half22float2(*(const __half2*)&u.x);
    float2 p1 = __half22float2(*(const __half2*)&u.y);
    float2 p2 = __half22float2(*(const __half2*)&u.z);
    float2 p3 = __half22float2(*(const __half2*)&u.w);
    a[0] += p0.x * w; a[1] += p0.y * w;
    a[2] += p1.x * w; a[3] += p1.y * w;
    a[4] += p2.x * w; a[5] += p2.y * w;
    a[6] += p3.x * w; a[7] += p3.y * w;
}

__global__ __launch_bounds__(128, 8) void seg_kernel(const float* __restrict__ b,
                                                     int N, int layer, int do_relu) {
    __shared__ unsigned smax[DF];
    int t = threadIdx.x;
    int lane = t & 31;
    int wrp = t >> 5;
    if (t < DF) smax[t] = 0u;
    __syncthreads();

    int d = blockIdx.x * 4 + wrp;
    if (d < N) {
        int beg = g_rowptr[d];
        int end = g_rowptr[d + 1];
        const uint4* sup = (const uint4*)g_support;   // 16 uint4 per row
        int half = lane >> 4;     // which edge of the pair this lane serves
        int sub = lane & 15;      // 16B slice within the row

        float acc0[8], acc1[8];
#pragma unroll
        for (int k = 0; k < 8; k++) { acc0[k] = 0.f; acc1[k] = 0.f; }

        for (int base = beg; base < end; base += 32) {
            int m = end - base;
            if (m > 32) m = 32;
            int2 dsc = make_int2(0, 0);
            if (lane < m) dsc = g_edge_s[base + lane];

            int j = 0;
            for (; j + 8 <= m; j += 8) {
                int e0 = j + half, e1 = j + 2 + half, e2 = j + 4 + half, e3 = j + 6 + half;
                int s0 = __shfl_sync(0xffffffffu, dsc.x, e0);
                int s1 = __shfl_sync(0xffffffffu, dsc.x, e1);
                int s2 = __shfl_sync(0xffffffffu, dsc.x, e2);
                int s3 = __shfl_sync(0xffffffffu, dsc.x, e3);
                float w0 = __int_as_float(__shfl_sync(0xffffffffu, dsc.y, e0));
                float w1 = __int_as_float(__shfl_sync(0xffffffffu, dsc.y, e1));
                float w2 = __int_as_float(__shfl_sync(0xffffffffu, dsc.y, e2));
                float w3 = __int_as_float(__shfl_sync(0xffffffffu, dsc.y, e3));
                uint4 u0 = sup[(size_t)s0 * 16 + sub];
                uint4 u1 = sup[(size_t)s1 * 16 + sub];
                uint4 u2 = sup[(size_t)s2 * 16 + sub];
                uint4 u3 = sup[(size_t)s3 * 16 + sub];
                fma8(acc0, u0, w0);
                fma8(acc1, u1, w1);
                fma8(acc0, u2, w2);
                fma8(acc1, u3, w3);
            }
            for (; j + 2 <= m; j += 2) {
                int e = j + half;
                int s0 = __shfl_sync(0xffffffffu, dsc.x, e);
                float w0 = __int_as_float(__shfl_sync(0xffffffffu, dsc.y, e));
                uint4 u0 = sup[(size_t)s0 * 16 + sub];
                fma8(acc0, u0, w0);
            }
            if (j < m) {   // odd leftover: handled by half 0 only
                int s0 = __shfl_sync(0xffffffffu, dsc.x, j);
                float w0 = __int_as_float(__shfl_sync(0xffffffffu, dsc.y, j));
                if (half == 0) {
                    uint4 u0 = sup[(size_t)s0 * 16 + sub];
                    fma8(acc0, u0, w0);
                }
            }
        }

        // Combine chains + cross-half partial sums.
        float r[8];
#pragma unroll
        for (int k = 0; k < 8; k++) {
            r[k] = acc0[k] + acc1[k];
            r[k] += __shfl_xor_sync(0xffffffffu, r[k], 16);
        }
        // This lane owns cols [sub*8 + half*4, +4).
        int col = sub * 8 + half * 4;
        float4 bv = *(const float4*)&b[col];
        float4 v = make_float4(r[half * 4 + 0] + bv.x, r[half * 4 + 1] + bv.y,
                               r[half * 4 + 2] + bv.z, r[half * 4 + 3] + bv.w);
        if (do_relu) {
            v.x = fmaxf(v.x, 0.f); v.y = fmaxf(v.y, 0.f);
            v.z = fmaxf(v.z, 0.f); v.w = fmaxf(v.w, 0.f);
            *(float4*)&g_h[(size_t)d * DF + col] = v;
        }
        atomicMax(&smax[col + 0], fenc(v.x));
        atomicMax(&smax[col + 1], fenc(v.y));
        atomicMax(&smax[col + 2], fenc(v.z));
        atomicMax(&smax[col + 3], fenc(v.w));
    }
    __syncthreads();
    if (t < DF) atomicMax(&g_okey[layer * DF + t], smax[t]);
}

// ---------------- head ----------------------------------------------------

__global__ __launch_bounds__(128) void final_kernel(const float* __restrict__ lin_W,
                                                    const float* __restrict__ lin_b,
                                                    float* __restrict__ out) {
    __shared__ float lin_in[3 * DF];
    __shared__ float logits[NCLS];
    int t = threadIdx.x;
    for (int i = t; i < 3 * DF; i += 128) lin_in[i] = fdec(g_okey[i]);
    __syncthreads();
    if (t < NCLS) {
        float s = lin_b[t];
#pragma unroll 4
        for (int j = 0; j < 3 * DF; j++) s += lin_W[t * 3 * DF + j] * lin_in[j];
        logits[t] = s;
    }
    __syncthreads();
    if (t == 0) {
        float m = -3.402823466e+38f;
        for (int c = 0; c < NCLS; c++) m = fmaxf(m, logits[c]);
        float se = 0.f;
        for (int c = 0; c < NCLS; c++) se += expf(logits[c] - m);
        float lse = m + logf(se);
        for (int c = 0; c < NCLS; c++) out[c] = logits[c] - lse;
    }
}

extern "C" void kernel_launch(void* const* d_in, const int* in_sizes, int n_in,
                              void* d_out, int out_size) {
    const float* x    = (const float*)d_in[0];
    const int*   esrc = (const int*)d_in[1];
    const int*   edst = (const int*)d_in[2];
    const float* ew   = (const float*)d_in[3];
    const float* W1   = (const float*)d_in[4];
    const float* b1   = (const float*)d_in[5];
    const float* W2   = (const float*)d_in[6];
    const float* b2   = (const float*)d_in[7];
    const float* W3   = (const float*)d_in[8];
    const float* b3   = (const float*)d_in[9];
    const float* linW = (const float*)d_in[10];
    const float* linb = (const float*)d_in[11];
    float* out = (float*)d_out;

    int N = in_sizes[0] / DF;
    int E = in_sizes[1];

    static int attr_set = 0;
    if (!attr_set) {
        cudaFuncSetAttribute(gemm_kernel, cudaFuncAttributeMaxDynamicSharedMemorySize, GEMM_SMEM);
        attr_set = 1;
    }

    int eb = (E + 255) / 256;
    int gemm_blocks = (N + 127) / 128;
    int seg_blocks = (N + 3) / 4;

    init_kernel<<<(N + 256) / 256, 256>>>(N);
    hist_kernel<<<eb, 256>>>(edst, E);
    scan_kernel<<<1, 1024>>>(N);
    reorder_kernel<<<eb, 256>>>(esrc, edst, ew, E);

    gemm_kernel<<<gemm_blocks, 256, GEMM_SMEM>>>(x, W1, N, 0);
    seg_kernel<<<seg_blocks, 128>>>(b1, N, 0, 1);
    gemm_kernel<<<gemm_blocks, 256, GEMM_SMEM>>>(nullptr, W2, N, 1);
    seg_kernel<<<seg_blocks, 128>>>(b2, N, 1, 1);
    gemm_kernel<<<gemm_blocks, 256, GEMM_SMEM>>>(nullptr, W3, N, 2);
    seg_kernel<<<seg_blocks, 128>>>(b3, N, 2, 0);
    final_kernel<<<1, 128>>>(linW, linb, out);
}

// round 8
// speedup vs baseline: 1.7013x; 1.7013x over previous
#include <cuda_runtime.h>
#include <cuda_fp16.h>
#include <cuda_bf16.h>

#define DF 128
#define NMAX 50000
#define EMAX 800000
#define NCLS 10
#define SCB 256                       // scan block size
#define NSCB ((NMAX + 1 + SCB - 1) / SCB)   // 196 blocks cover N+1 entries

// Scratch (allocation-free __device__ globals).
__device__ __align__(16) __half g_support[(size_t)NMAX * DF];   // fp16 gather source
__device__ __align__(16) float  g_h[(size_t)NMAX * DF];         // fp32 layer activations
__device__ __align__(16) int2   g_edge_s[EMAX];                 // sorted-by-dst (src, bits(w))
__device__ int g_cnt[NMAX + 1];
__device__ int g_rowptr[NMAX + 1];
__device__ int g_cur[NMAX + 1];
__device__ int g_blksum[NSCB];
__device__ int g_blkoff[NSCB];
__device__ unsigned g_okey[3 * DF];

__device__ __forceinline__ unsigned fenc(float x) {
    unsigned u = __float_as_uint(x);
    return (u & 0x80000000u) ? ~u : (u | 0x80000000u);
}
__device__ __forceinline__ float fdec(unsigned k) {
    unsigned u = (k & 0x80000000u) ? (k & 0x7FFFFFFFu) : ~k;
    return __uint_as_float(u);
}
__device__ __forceinline__ unsigned smem_u32(const void* p) {
    return (unsigned)__cvta_generic_to_shared(p);
}

// ---------------- sort: counting sort of edges by dst -------------------

__global__ __launch_bounds__(256) void init_kernel(int N) {
    int i = blockIdx.x * 256 + threadIdx.x;
    if (i <= N) g_cnt[i] = 0;
    if (i < 3 * DF) g_okey[i] = 0u;
}

__global__ __launch_bounds__(256) void hist_kernel(const int* __restrict__ dst, int E) {
    int e = blockIdx.x * 256 + threadIdx.x;
    if (e < E) atomicAdd(&g_cnt[dst[e]], 1);
}

// Phase 1: per-block sums of g_cnt[0..N] (values beyond N treated as 0).
__global__ __launch_bounds__(SCB) void scan1_kernel(int N) {
    __shared__ int sh[SCB];
    int t = threadIdx.x;
    int idx = blockIdx.x * SCB + t;
    int v = (idx < N) ? g_cnt[idx] : 0;   // exclusive of idx==N sentinel
    sh[t] = v;
    __syncthreads();
    for (int off = SCB / 2; off > 0; off >>= 1) {
        if (t < off) sh[t] += sh[t + off];
        __syncthreads();
    }
    if (t == 0) g_blksum[blockIdx.x] = sh[0];
}

// Phase 2: one block exclusive-scans the NSCB partials.
__global__ __launch_bounds__(SCB) void scan2_kernel() {
    __shared__ int sh[SCB];
    int t = threadIdx.x;
    sh[t] = (t < NSCB) ? g_blksum[t] : 0;
    __syncthreads();
    for (int off = 1; off < SCB; off <<= 1) {
        int v = sh[t];
        int add = (t >= off) ? sh[t - off] : 0;
        __syncthreads();
        sh[t] = v + add;
        __syncthreads();
    }
    if (t < NSCB) g_blkoff[t] = (t == 0) ? 0 : sh[t - 1];
}

// Phase 3: block-local exclusive scan + block offset -> rowptr/cur.
__global__ __launch_bounds__(SCB) void scan3_kernel(int N) {
    __shared__ int sh[SCB];
    int t = threadIdx.x;
    int idx = blockIdx.x * SCB + t;
    int v = (idx < N) ? g_cnt[idx] : 0;
    sh[t] = v;
    __syncthreads();
    for (int off = 1; off < SCB; off <<= 1) {
        int x = sh[t];
        int add = (t >= off) ? sh[t - off] : 0;
        __syncthreads();
        sh[t] = x + add;
        __syncthreads();
    }
    if (idx <= N) {
        int excl = g_blkoff[blockIdx.x] + sh[t] - v;   // inclusive - self = exclusive
        g_rowptr[idx] = excl;
        if (idx < N) g_cur[idx] = excl;
    }
}

__global__ __launch_bounds__(256) void reorder_kernel(const int* __restrict__ src,
                                                      const int* __restrict__ dst,
                                                      const float* __restrict__ w,
                                                      int E) {
    int e = blockIdx.x * 256 + threadIdx.x;
    if (e >= E) return;
    int d = dst[e];
    int pos = atomicAdd(&g_cur[d], 1);
    g_edge_s[pos] = make_int2(src[e], __float_as_int(w[e]));
}

// ---------------- GEMM: support(fp16) = Ain(fp32) @ W, fp16 m16n8k16 mma ---

#define SH 136
#define GEMM_SMEM (2 * DF * SH * (int)sizeof(__half))  // 69632 B

__global__ __launch_bounds__(256, 2) void gemm_kernel(const float* __restrict__ A,
                                                      const float* __restrict__ W,
                                                      int N, int use_gh) {
    extern __shared__ __half smem_h[];
    __half* Ws = smem_h;             // [128 k][136 n]
    __half* As = smem_h + DF * SH;   // [128 m][136 k]
    const float* Ain = use_gh ? g_h : A;

    int t = threadIdx.x;
    int lane = t & 31;
    int wrp = t >> 5;
    int wm = wrp >> 1;
    int wn = wrp & 1;
    int r0 = blockIdx.x * 128;

    for (int i = t; i < DF * 32; i += 256) {
        int k = i >> 5;
        int n4 = (i & 31) * 4;
        float4 wv = *(const float4*)&W[k * DF + n4];
        __half2* dstp = (__half2*)&Ws[k * SH + n4];
        dstp[0] = __floats2half2_rn(wv.x, wv.y);
        dstp[1] = __floats2half2_rn(wv.z, wv.w);
    }
    for (int i = t; i < DF * 32; i += 256) {
        int row = i >> 5;
        int k4 = (i & 31) * 4;
        int gr = r0 + row;
        float4 av = make_float4(0.f, 0.f, 0.f, 0.f);
        if (gr < N) av = *(const float4*)&Ain[(size_t)gr * DF + k4];
        __half2* dstp = (__half2*)&As[row * SH + k4];
        dstp[0] = __floats2half2_rn(av.x, av.y);
        dstp[1] = __floats2half2_rn(av.z, av.w);
    }
    __syncthreads();

    float acc[2][8][4];
#pragma unroll
    for (int mt = 0; mt < 2; mt++)
#pragma unroll
        for (int nt = 0; nt < 8; nt++)
#pragma unroll
            for (int r = 0; r < 4; r++) acc[mt][nt][r] = 0.f;

    int gid = lane >> 2;
    int tig = lane & 3;

    int tr = lane & 7;
    int tile = lane >> 3;
    int row_off = (tile & 1) ? 8 : 0;
    int col_off = (tile & 2) ? 8 : 0;
    unsigned addrA[2];
#pragma unroll
    for (int mt = 0; mt < 2; mt++) {
        int m0 = wm * 32 + mt * 16;
        addrA[mt] = smem_u32(&As[(m0 + tr + row_off) * SH + col_off]);
    }
    unsigned addrB[4];
#pragma unroll
    for (int np = 0; np < 4; np++) {
        int nb = wn * 64 + np * 16;
        addrB[np] = smem_u32(&Ws[(tr + row_off) * SH + nb + col_off]);
    }

#pragma unroll
    for (int ks = 0; ks < 8; ks++) {
        unsigned af[2][4];
#pragma unroll
        for (int mt = 0; mt < 2; mt++) {
            asm volatile(
                "ldmatrix.sync.aligned.m8n8.x4.shared.b16 {%0,%1,%2,%3}, [%4];"
                : "=r"(af[mt][0]), "=r"(af[mt][1]), "=r"(af[mt][2]), "=r"(af[mt][3])
                : "r"(addrA[mt] + ks * 16 * (unsigned)sizeof(__half)));
        }
        unsigned bf[4][4];
#pragma unroll
        for (int np = 0; np < 4; np++) {
            asm volatile(
                "ldmatrix.sync.aligned.m8n8.x4.trans.shared.b16 {%0,%1,%2,%3}, [%4];"
                : "=r"(bf[np][0]), "=r"(bf[np][1]), "=r"(bf[np][2]), "=r"(bf[np][3])
                : "r"(addrB[np] + ks * 16 * SH * (unsigned)sizeof(__half)));
        }
#pragma unroll
        for (int np = 0; np < 4; np++) {
#pragma unroll
            for (int sub = 0; sub < 2; sub++) {
                int nt = np * 2 + sub;
#pragma unroll
                for (int mt = 0; mt < 2; mt++) {
                    asm volatile(
                        "mma.sync.aligned.m16n8k16.row.col.f32.f16.f16.f32 "
                        "{%0,%1,%2,%3}, {%4,%5,%6,%7}, {%8,%9}, {%0,%1,%2,%3};"
                        : "+f"(acc[mt][nt][0]), "+f"(acc[mt][nt][1]),
                          "+f"(acc[mt][nt][2]), "+f"(acc[mt][nt][3])
                        : "r"(af[mt][0]), "r"(af[mt][1]),
                          "r"(af[mt][2]), "r"(af[mt][3]),
                        "r"(bf[np][sub * 2]), "r"(bf[np][sub * 2 + 1]));
                }
            }
        }
    }

#pragma unroll
    for (int mt = 0; mt < 2; mt++) {
#pragma unroll
        for (int nt = 0; nt < 8; nt++) {
            int row = r0 + wm * 32 + mt * 16 + gid;
            int col = wn * 64 + nt * 8 + 2 * tig;
            if (row < N)
                *(__half2*)&g_support[(size_t)row * DF + col] =
                    __floats2half2_rn(acc[mt][nt][0], acc[mt][nt][1]);
            if (row + 8 < N)
                *(__half2*)&g_support[(size_t)(row + 8) * DF + col] =
                    __floats2half2_rn(acc[mt][nt][2], acc[mt][nt][3]);
        }
    }
}

// ---------------- segment-sum + bias (+relu, h write) + column max --------
// R5 form: one warp per dst row; coalesced descriptor load + shfl; 8-wide MLP.

__device__ __forceinline__ void edge_fma(float4& a, const uint2 u, const float w) {
    float2 lo = __half22float2(*(const __half2*)&u.x);
    float2 hi = __half22float2(*(const __half2*)&u.y);
    a.x += lo.x * w; a.y += lo.y * w;
    a.z += hi.x * w; a.w += hi.y * w;
}

__global__ __launch_bounds__(256) void seg_kernel(const float* __restrict__ b,
                                                  int N, int layer, int do_relu) {
    __shared__ unsigned smax[DF];
    int t = threadIdx.x;
    int lane = t & 31;
    int wrp = t >> 5;
    if (t < DF) smax[t] = 0u;
    __syncthreads();

    int d = blockIdx.x * 8 + wrp;
    if (d < N) {
        int beg = g_rowptr[d];
        int end = g_rowptr[d + 1];
        const uint2* sup = (const uint2*)g_support;

        float4 acc0 = make_float4(0.f, 0.f, 0.f, 0.f);
        float4 acc1 = make_float4(0.f, 0.f, 0.f, 0.f);

        for (int base = beg; base < end; base += 32) {
            int m = end - base;
            if (m > 32) m = 32;
            int2 dsc = make_int2(0, 0);
            if (lane < m) dsc = g_edge_s[base + lane];

            int j = 0;
            for (; j + 8 <= m; j += 8) {
                int s0 = __shfl_sync(0xffffffffu, dsc.x, j + 0);
                int s1 = __shfl_sync(0xffffffffu, dsc.x, j + 1);
                int s2 = __shfl_sync(0xffffffffu, dsc.x, j + 2);
                int s3 = __shfl_sync(0xffffffffu, dsc.x, j + 3);
                int s4 = __shfl_sync(0xffffffffu, dsc.x, j + 4);
                int s5 = __shfl_sync(0xffffffffu, dsc.x, j + 5);
                int s6 = __shfl_sync(0xffffffffu, dsc.x, j + 6);
                int s7 = __shfl_sync(0xffffffffu, dsc.x, j + 7);
                float w0 = __int_as_float(__shfl_sync(0xffffffffu, dsc.y, j + 0));
                float w1 = __int_as_float(__shfl_sync(0xffffffffu, dsc.y, j + 1));
                float w2 = __int_as_float(__shfl_sync(0xffffffffu, dsc.y, j + 2));
                float w3 = __int_as_float(__shfl_sync(0xffffffffu, dsc.y, j + 3));
                float w4 = __int_as_float(__shfl_sync(0xffffffffu, dsc.y, j + 4));
                float w5 = __int_as_float(__shfl_sync(0xffffffffu, dsc.y, j + 5));
                float w6 = __int_as_float(__shfl_sync(0xffffffffu, dsc.y, j + 6));
                float w7 = __int_as_float(__shfl_sync(0xffffffffu, dsc.y, j + 7));
                uint2 u0 = sup[(size_t)s0 * 32 + lane];
                uint2 u1 = sup[(size_t)s1 * 32 + lane];
                uint2 u2 = sup[(size_t)s2 * 32 + lane];
                uint2 u3 = sup[(size_t)s3 * 32 + lane];
                uint2 u4 = sup[(size_t)s4 * 32 + lane];
                uint2 u5 = sup[(size_t)s5 * 32 + lane];
                uint2 u6 = sup[(size_t)s6 * 32 + lane];
                uint2 u7 = sup[(size_t)s7 * 32 + lane];
                edge_fma(acc0, u0, w0);
                edge_fma(acc1, u1, w1);
                edge_fma(acc0, u2, w2);
                edge_fma(acc1, u3, w3);
                edge_fma(acc0, u4, w4);
                edge_fma(acc1, u5, w5);
                edge_fma(acc0, u6, w6);
                edge_fma(acc1, u7, w7);
            }
            for (; j + 2 <= m; j += 2) {
                int s0 = __shfl_sync(0xffffffffu, dsc.x, j + 0);
                int s1 = __shfl_sync(0xffffffffu, dsc.x, j + 1);
                float w0 = __int_as_float(__shfl_sync(0xffffffffu, dsc.y, j + 0));
                float w1 = __int_as_float(__shfl_sync(0xffffffffu, dsc.y, j + 1));
                uint2 u0 = sup[(size_t)s0 * 32 + lane];
                uint2 u1 = sup[(size_t)s1 * 32 + lane];
                edge_fma(acc0, u0, w0);
                edge_fma(acc1, u1, w1);
            }
            if (j < m) {
                int s0 = __shfl_sync(0xffffffffu, dsc.x, j);
                float w0 = __int_as_float(__shfl_sync(0xffffffffu, dsc.y, j));
                uint2 u0 = sup[(size_t)s0 * 32 + lane];
                edge_fma(acc0, u0, w0);
            }
        }

        float4 v;
        const float4* bb = (const float4*)b;
        float4 bv = bb[lane];
        v.x = acc0.x + acc1.x + bv.x;
        v.y = acc0.y + acc1.y + bv.y;
        v.z = acc0.z + acc1.z + bv.z;
        v.w = acc0.w + acc1.w + bv.w;
        if (do_relu) {
            v.x = fmaxf(v.x, 0.f); v.y = fmaxf(v.y, 0.f);
            v.z = fmaxf(v.z, 0.f); v.w = fmaxf(v.w, 0.f);
            *(float4*)&g_h[(size_t)d * DF + lane * 4] = v;
        }
        atomicMax(&smax[lane * 4 + 0], fenc(v.x));
        atomicMax(&smax[lane * 4 + 1], fenc(v.y));
        atomicMax(&smax[lane * 4 + 2], fenc(v.z));
        atomicMax(&smax[lane * 4 + 3], fenc(v.w));
    }
    __syncthreads();
    if (t < DF) atomicMax(&g_okey[layer * DF + t], smax[t]);
}

// ---------------- head ----------------------------------------------------

__global__ __launch_bounds__(128) void final_kernel(const float* __restrict__ lin_W,
                                                    const float* __restrict__ lin_b,
                                                    float* __restrict__ out) {
    __shared__ float lin_in[3 * DF];
    __shared__ float logits[NCLS];
    int t = threadIdx.x;
    for (int i = t; i < 3 * DF; i += 128) lin_in[i] = fdec(g_okey[i]);
    __syncthreads();
    if (t < NCLS) {
        float s = lin_b[t];
#pragma unroll 4
        for (int j = 0; j < 3 * DF; j++) s += lin_W[t * 3 * DF + j] * lin_in[j];
        logits[t] = s;
    }
    __syncthreads();
    if (t == 0) {
        float m = -3.402823466e+38f;
        for (int c = 0; c < NCLS; c++) m = fmaxf(m, logits[c]);
        float se = 0.f;
        for (int c = 0; c < NCLS; c++) se += expf(logits[c] - m);
        float lse = m + logf(se);
        for (int c = 0; c < NCLS; c++) out[c] = logits[c] - lse;
    }
}

extern "C" void kernel_launch(void* const* d_in, const int* in_sizes, int n_in,
                              void* d_out, int out_size) {
    const float* x    = (const float*)d_in[0];
    const int*   esrc = (const int*)d_in[1];
    const int*   edst = (const int*)d_in[2];
    const float* ew   = (const float*)d_in[3];
    const float* W1   = (const float*)d_in[4];
    const float* b1   = (const float*)d_in[5];
    const float* W2   = (const float*)d_in[6];
    const float* b2   = (const float*)d_in[7];
    const float* W3   = (const float*)d_in[8];
    const float* b3   = (const float*)d_in[9];
    const float* linW = (const float*)d_in[10];
    const float* linb = (const float*)d_in[11];
    float* out = (float*)d_out;

    int N = in_sizes[0] / DF;
    int E = in_sizes[1];

    static int attr_set = 0;
    if (!attr_set) {
        cudaFuncSetAttribute(gemm_kernel, cudaFuncAttributeMaxDynamicSharedMemorySize, GEMM_SMEM);
        attr_set = 1;
    }

    int eb = (E + 255) / 256;
    int gemm_blocks = (N + 127) / 128;
    int seg_blocks = (N + 7) / 8;
    int scan_blocks = (N + 1 + SCB - 1) / SCB;

    // Launch order puts gemm1 (independent of the sort) in the ncu capture
    // slot (4th kernel of this graph).
    init_kernel<<<(N + 256) / 256, 256>>>(N);                    // 1
    hist_kernel<<<eb, 256>>>(edst, E);                           // 2
    scan1_kernel<<<scan_blocks, SCB>>>(N);                       // 3
    gemm_kernel<<<gemm_blocks, 256, GEMM_SMEM>>>(x, W1, N, 0);   // 4 <- capture
    scan2_kernel<<<1, SCB>>>();                                  // 5
    scan3_kernel<<<scan_blocks, SCB>>>(N);                       // 6
    reorder_kernel<<<eb, 256>>>(esrc, edst, ew, E);              // 7

    seg_kernel<<<seg_blocks, 256>>>(b1, N, 0, 1);
    gemm_kernel<<<gemm_blocks, 256, GEMM_SMEM>>>(nullptr, W2, N, 1);
    seg_kernel<<<seg_blocks, 256>>>(b2, N, 1, 1);
    gemm_kernel<<<gemm_blocks, 256, GEMM_SMEM>>>(nullptr, W3, N, 2);
    seg_kernel<<<seg_blocks, 256>>>(b3, N, 2, 0);
    final_kernel<<<1, 128>>>(linW, linb, out);
}

// round 14
// speedup vs baseline: 1.9084x; 1.1217x over previous
#include <cuda_runtime.h>
#include <cuda_fp16.h>
#include <cuda_bf16.h>
#include <cstdint>

#define DF 128
#define NMAX 50000
#define EMAX 800000
#define NCLS 10
#define SCB 256
#define NSCB ((NMAX + 1 + SCB - 1) / SCB)

// Scratch (allocation-free __device__ globals).
__device__ __align__(16) __half g_support[(size_t)NMAX * DF];  // gemm out / seg in
__device__ __align__(16) __half g_ah[(size_t)NMAX * DF];       // fp16 activations (gemm A input)
__device__ __align__(16) __half g_w16[3 * DF * DF];            // fp16 weights
__device__ __align__(16) int2   g_edge_s[EMAX];
__device__ int g_cnt[NMAX + 1];
__device__ int g_rowptr[NMAX + 1];
__device__ int g_cur[NMAX + 1];
__device__ int g_blksum[NSCB];
__device__ int g_blkoff[NSCB];
__device__ unsigned g_okey[3 * DF];

__device__ __forceinline__ unsigned fenc(float x) {
    unsigned u = __float_as_uint(x);
    return (u & 0x80000000u) ? ~u : (u | 0x80000000u);
}
__device__ __forceinline__ float fdec(unsigned k) {
    unsigned u = (k & 0x80000000u) ? (k & 0x7FFFFFFFu) : ~k;
    return __uint_as_float(u);
}
__device__ __forceinline__ unsigned smem_u32(const void* p) {
    return (unsigned)__cvta_generic_to_shared(p);
}
__device__ __forceinline__ unsigned h2_as_u32(__half2 h) {
    return *reinterpret_cast<unsigned*>(&h);
}

// ---------------- prep: one-time fp32->fp16 conversion of x and W1/2/3 -----

__global__ __launch_bounds__(256) void prep_kernel(const float* __restrict__ x,
                                                   const float* __restrict__ W1,
                                                   const float* __restrict__ W2,
                                                   const float* __restrict__ W3,
                                                   int N) {
    long total = (long)N * 32;          // N*128 floats as float4
    for (long i = (long)blockIdx.x * 256 + threadIdx.x; i < total;
         i += (long)gridDim.x * 256) {
        float4 v = ((const float4*)x)[i];
        uint2 pk;
        pk.x = h2_as_u32(__floats2half2_rn(v.x, v.y));
        pk.y = h2_as_u32(__floats2half2_rn(v.z, v.w));
        ((uint2*)g_ah)[i] = pk;
    }
    // W conversion: 3 * 128*128/4 = 12288 float4s.
    for (int i = blockIdx.x * 256 + threadIdx.x; i < 3 * DF * 32;
         i += gridDim.x * 256) {
        const float* Wsrc = (i < DF * 32) ? W1 : (i < 2 * DF * 32) ? W2 : W3;
        int li = i & (DF * 32 - 1);     // DF*32 = 4096, power of two
        float4 v = ((const float4*)Wsrc)[li];
        uint2 pk;
        pk.x = h2_as_u32(__floats2half2_rn(v.x, v.y));
        pk.y = h2_as_u32(__floats2half2_rn(v.z, v.w));
        ((uint2*)g_w16)[i] = pk;
    }
}

// ---------------- sort: counting sort of edges by dst -------------------

__global__ __launch_bounds__(256) void init_kernel(int N) {
    int i = blockIdx.x * 256 + threadIdx.x;
    if (i <= N) g_cnt[i] = 0;
    if (i < 3 * DF) g_okey[i] = 0u;
}

__global__ __launch_bounds__(256) void hist_kernel(const int* __restrict__ dst, int E) {
    int e = blockIdx.x * 256 + threadIdx.x;
    if (e < E) atomicAdd(&g_cnt[dst[e]], 1);
}

__global__ __launch_bounds__(SCB) void scan1_kernel(int N) {
    __shared__ int sh[SCB];
    int t = threadIdx.x;
    int idx = blockIdx.x * SCB + t;
    int v = (idx < N) ? g_cnt[idx] : 0;
    sh[t] = v;
    __syncthreads();
    for (int off = SCB / 2; off > 0; off >>= 1) {
        if (t < off) sh[t] += sh[t + off];
        __syncthreads();
    }
    if (t == 0) g_blksum[blockIdx.x] = sh[0];
}

__global__ __launch_bounds__(SCB) void scan2_kernel() {
    __shared__ int sh[SCB];
    int t = threadIdx.x;
    sh[t] = (t < NSCB) ? g_blksum[t] : 0;
    __syncthreads();
    for (int off = 1; off < SCB; off <<= 1) {
        int v = sh[t];
        int add = (t >= off) ? sh[t - off] : 0;
        __syncthreads();
        sh[t] = v + add;
        __syncthreads();
    }
    if (t < NSCB) g_blkoff[t] = (t == 0) ? 0 : sh[t - 1];
}

__global__ __launch_bounds__(SCB) void scan3_kernel(int N) {
    __shared__ int sh[SCB];
    int t = threadIdx.x;
    int idx = blockIdx.x * SCB + t;
    int v = (idx < N) ? g_cnt[idx] : 0;
    sh[t] = v;
    __syncthreads();
    for (int off = 1; off < SCB; off <<= 1) {
        int x = sh[t];
        int add = (t >= off) ? sh[t - off] : 0;
        __syncthreads();
        sh[t] = x + add;
        __syncthreads();
    }
    if (idx <= N) {
        int excl = g_blkoff[blockIdx.x] + sh[t] - v;
        g_rowptr[idx] = excl;
        if (idx < N) g_cur[idx] = excl;
    }
}

__global__ __launch_bounds__(256) void reorder_kernel(const int* __restrict__ src,
                                                      const int* __restrict__ dst,
                                                      const float* __restrict__ w,
                                                      int E) {
    int e = blockIdx.x * 256 + threadIdx.x;
    if (e >= E) return;
    int d = dst[e];
    int pos = atomicAdd(&g_cur[d], 1);
    g_edge_s[pos] = make_int2(src[e], __float_as_int(w[e]));
}

// ---------------- GEMM: support(fp16) = g_ah(fp16) @ g_w16[layer] ----------
// Block tile 128(m) x 64(n); 8 warps, warp tile 32x32 = 2(m) x 4(n) m16n8k16.
// All-fp16 staging (no conversions); 3 CTAs/SM.

#define SA 136   // A smem stride (halves)
#define SW 72    // W smem stride (halves)
#define GEMM_SMEM ((DF * SA + DF * SW) * (int)sizeof(__half))  // 53248 B

__global__ __launch_bounds__(256, 3) void gemm_kernel(int N, int layer) {
    extern __shared__ __half smem_h[];
    __half* As = smem_h;             // [128 m][136] (k)
    __half* Ws = smem_h + DF * SA;   // [128 k][72] (n half)

    int t = threadIdx.x;
    int lane = t & 31;
    int wrp = t >> 5;
    int wm = wrp & 3;        // m quarter (32 rows)
    int wn = wrp >> 2;       // n 32-col chunk within the 64-col half
    int rb = blockIdx.x >> 1;
    int nh = blockIdx.x & 1; // which 64-col half of the output
    int r0 = rb * 128;

    const __half* Wg = g_w16 + layer * DF * DF;

    // Stage A [128 m][128 k] fp16: 16 x 16B chunks per row.
    for (int i = t; i < DF * 16; i += 256) {
        int row = i >> 4;
        int sg = (i & 15) * 8;     // half index within row
        int gr = r0 + row;
        uint4 v = make_uint4(0u, 0u, 0u, 0u);
        if (gr < N) v = *(const uint4*)&g_ah[(size_t)gr * DF + sg];
        *(uint4*)&As[row * SA + sg] = v;
    }
    // Stage W half [128 k][64 n] fp16: 8 x 16B chunks per row.
    for (int i = t; i < DF * 8; i += 256) {
        int k = i >> 3;
        int sg = (i & 7) * 8;
        uint4 v = *(const uint4*)&Wg[k * DF + nh * 64 + sg];
        *(uint4*)&Ws[k * SW + sg] = v;
    }
    __syncthreads();

    float acc[2][4][4];
#pragma unroll
    for (int mt = 0; mt < 2; mt++)
#pragma unroll
        for (int nt = 0; nt < 4; nt++)
#pragma unroll
            for (int r = 0; r < 4; r++) acc[mt][nt][r] = 0.f;

    int gid = lane >> 2;
    int tig = lane & 3;
    int tr = lane & 7;
    int tile = lane >> 3;
    int row_off = (tile & 1) ? 8 : 0;
    int col_off = (tile & 2) ? 8 : 0;

    unsigned addrA[2];
#pragma unroll
    for (int mt = 0; mt < 2; mt++) {
        int m0 = wm * 32 + mt * 16;
        addrA[mt] = smem_u32(&As[(m0 + tr + row_off) * SA + col_off]);
    }
    unsigned addrB[2];
#pragma unroll
    for (int np = 0; np < 2; np++) {
        int nb = wn * 32 + np * 16;
        addrB[np] = smem_u32(&Ws[(tr + row_off) * SW + nb + col_off]);
    }

#pragma unroll
    for (int ks = 0; ks < 8; ks++) {
        unsigned af[2][4];
#pragma unroll
        for (int mt = 0; mt < 2; mt++) {
            asm volatile(
                "ldmatrix.sync.aligned.m8n8.x4.shared.b16 {%0,%1,%2,%3}, [%4];"
                : "=r"(af[mt][0]), "=r"(af[mt][1]), "=r"(af[mt][2]), "=r"(af[mt][3])
                : "r"(addrA[mt] + ks * 16 * (unsigned)sizeof(__half)));
        }
        unsigned bf[2][4];
#pragma unroll
        for (int np = 0; np < 2; np++) {
            asm volatile(
                "ldmatrix.sync.aligned.m8n8.x4.trans.shared.b16 {%0,%1,%2,%3}, [%4];"
                : "=r"(bf[np][0]), "=r"(bf[np][1]), "=r"(bf[np][2]), "=r"(bf[np][3])
                : "r"(addrB[np] + ks * 16 * SW * (unsigned)sizeof(__half)));
        }
#pragma unroll
        for (int np = 0; np < 2; np++) {
#pragma unroll
            for (int sub = 0; sub < 2; sub++) {
                int nt = np * 2 + sub;
#pragma unroll
                for (int mt = 0; mt < 2; mt++) {
                    asm volatile(
                        "mma.sync.aligned.m16n8k16.row.col.f32.f16.f16.f32 "
                        "{%0,%1,%2,%3}, {%4,%5,%6,%7}, {%8,%9}, {%0,%1,%2,%3};"
                        : "+f"(acc[mt][nt][0]), "+f"(acc[mt][nt][1]),
                          "+f"(acc[mt][nt][2]), "+f"(acc[mt][nt][3])
                        : "r"(af[mt][0]), "r"(af[mt][1]),
                          "r"(af[mt][2]), "r"(af[mt][3]),
                        "r"(bf[np][sub * 2]), "r"(bf[np][sub * 2 + 1]));
                }
            }
        }
    }

#pragma unroll
    for (int mt = 0; mt < 2; mt++) {
#pragma unroll
        for (int nt = 0; nt < 4; nt++) {
            int row = r0 + wm * 32 + mt * 16 + gid;
            int col = nh * 64 + wn * 32 + nt * 8 + 2 * tig;
            if (row < N)
                *(__half2*)&g_support[(size_t)row * DF + col] =
                    __floats2half2_rn(acc[mt][nt][0], acc[mt][nt][1]);
            if (row + 8 < N)
                *(__half2*)&g_support[(size_t)(row + 8) * DF + col] =
                    __floats2half2_rn(acc[mt][nt][2], acc[mt][nt][3]);
        }
    }
}

// ---------------- segment-sum + bias (+relu, fp16 h write) + column max ----

__device__ __forceinline__ void edge_fma(float4& a, const uint2 u, const float w) {
    float2 lo = __half22float2(*(const __half2*)&u.x);
    float2 hi = __half22float2(*(const __half2*)&u.y);
    a.x += lo.x * w; a.y += lo.y * w;
    a.z += hi.x * w; a.w += hi.y * w;
}

__global__ __launch_bounds__(256) void seg_kernel(const float* __restrict__ b,
                                                  int N, int layer, int do_relu) {
    __shared__ unsigned smax[DF];
    int t = threadIdx.x;
    int lane = t & 31;
    int wrp = t >> 5;
    if (t < DF) smax[t] = 0u;
    __syncthreads();

    int d = blockIdx.x * 8 + wrp;
    if (d < N) {
        int beg = g_rowptr[d];
        int end = g_rowptr[d + 1];
        const uint2* sup = (const uint2*)g_support;

        float4 acc0 = make_float4(0.f, 0.f, 0.f, 0.f);
        float4 acc1 = make_float4(0.f, 0.f, 0.f, 0.f);

        for (int base = beg; base < end; base += 32) {
            int m = end - base;
            if (m > 32) m = 32;
            int2 dsc = make_int2(0, 0);
            if (lane < m) dsc = g_edge_s[base + lane];

            int j = 0;
            for (; j + 8 <= m; j += 8) {
                int s0 = __shfl_sync(0xffffffffu, dsc.x, j + 0);
                int s1 = __shfl_sync(0xffffffffu, dsc.x, j + 1);
                int s2 = __shfl_sync(0xffffffffu, dsc.x, j + 2);
                int s3 = __shfl_sync(0xffffffffu, dsc.x, j + 3);
                int s4 = __shfl_sync(0xffffffffu, dsc.x, j + 4);
                int s5 = __shfl_sync(0xffffffffu, dsc.x, j + 5);
                int s6 = __shfl_sync(0xffffffffu, dsc.x, j + 6);
                int s7 = __shfl_sync(0xffffffffu, dsc.x, j + 7);
                float w0 = __int_as_float(__shfl_sync(0xffffffffu, dsc.y, j + 0));
                float w1 = __int_as_float(__shfl_sync(0xffffffffu, dsc.y, j + 1));
                float w2 = __int_as_float(__shfl_sync(0xffffffffu, dsc.y, j + 2));
                float w3 = __int_as_float(__shfl_sync(0xffffffffu, dsc.y, j + 3));
                float w4 = __int_as_float(__shfl_sync(0xffffffffu, dsc.y, j + 4));
                float w5 = __int_as_float(__shfl_sync(0xffffffffu, dsc.y, j + 5));
                float w6 = __int_as_float(__shfl_sync(0xffffffffu, dsc.y, j + 6));
                float w7 = __int_as_float(__shfl_sync(0xffffffffu, dsc.y, j + 7));
                uint2 u0 = sup[(size_t)s0 * 32 + lane];
                uint2 u1 = sup[(size_t)s1 * 32 + lane];
                uint2 u2 = sup[(size_t)s2 * 32 + lane];
                uint2 u3 = sup[(size_t)s3 * 32 + lane];
                uint2 u4 = sup[(size_t)s4 * 32 + lane];
                uint2 u5 = sup[(size_t)s5 * 32 + lane];
                uint2 u6 = sup[(size_t)s6 * 32 + lane];
                uint2 u7 = sup[(size_t)s7 * 32 + lane];
                edge_fma(acc0, u0, w0);
                edge_fma(acc1, u1, w1);
                edge_fma(acc0, u2, w2);
                edge_fma(acc1, u3, w3);
                edge_fma(acc0, u4, w4);
                edge_fma(acc1, u5, w5);
                edge_fma(acc0, u6, w6);
                edge_fma(acc1, u7, w7);
            }
            for (; j + 2 <= m; j += 2) {
                int s0 = __shfl_sync(0xffffffffu, dsc.x, j + 0);
                int s1 = __shfl_sync(0xffffffffu, dsc.x, j + 1);
                float w0 = __int_as_float(__shfl_sync(0xffffffffu, dsc.y, j + 0));
                float w1 = __int_as_float(__shfl_sync(0xffffffffu, dsc.y, j + 1));
                uint2 u0 = sup[(size_t)s0 * 32 + lane];
                uint2 u1 = sup[(size_t)s1 * 32 + lane];
                edge_fma(acc0, u0, w0);
                edge_fma(acc1, u1, w1);
            }
            if (j < m) {
                int s0 = __shfl_sync(0xffffffffu, dsc.x, j);
                float w0 = __int_as_float(__shfl_sync(0xffffffffu, dsc.y, j));
                uint2 u0 = sup[(size_t)s0 * 32 + lane];
                edge_fma(acc0, u0, w0);
            }
        }

        float4 v;
        const float4* bb = (const float4*)b;
        float4 bv = bb[lane];
        v.x = acc0.x + acc1.x + bv.x;
        v.y = acc0.y + acc1.y + bv.y;
        v.z = acc0.z + acc1.z + bv.z;
        v.w = acc0.w + acc1.w + bv.w;
        if (do_relu) {
            v.x = fmaxf(v.x, 0.f); v.y = fmaxf(v.y, 0.f);
            v.z = fmaxf(v.z, 0.f); v.w = fmaxf(v.w, 0.f);
            // fp16 activation write (gemm input)
            uint2 pk;
            pk.x = h2_as_u32(__floats2half2_rn(v.x, v.y));
            pk.y = h2_as_u32(__floats2half2_rn(v.z, v.w));
            *(uint2*)&g_ah[(size_t)d * DF + lane * 4] = pk;
        }
        atomicMax(&smax[lane * 4 + 0], fenc(v.x));
        atomicMax(&smax[lane * 4 + 1], fenc(v.y));
        atomicMax(&smax[lane * 4 + 2], fenc(v.z));
        atomicMax(&smax[lane * 4 + 3], fenc(v.w));
    }
    __syncthreads();
    if (t < DF) atomicMax(&g_okey[layer * DF + t], smax[t]);
}

// ---------------- head ----------------------------------------------------

__global__ __launch_bounds__(128) void final_kernel(const float* __restrict__ lin_W,
                                                    const float* __restrict__ lin_b,
                                                    float* __restrict__ out) {
    __shared__ float lin_in[3 * DF];
    __shared__ float logits[NCLS];
    int t = threadIdx.x;
    for (int i = t; i < 3 * DF; i += 128) lin_in[i] = fdec(g_okey[i]);
    __syncthreads();
    if (t < NCLS) {
        float s = lin_b[t];
#pragma unroll 4
        for (int j = 0; j < 3 * DF; j++) s += lin_W[t * 3 * DF + j] * lin_in[j];
        logits[t] = s;
    }
    __syncthreads();
    if (t == 0) {
        float m = -3.402823466e+38f;
        for (int c = 0; c < NCLS; c++) m = fmaxf(m, logits[c]);
        float se = 0.f;
        for (int c = 0; c < NCLS; c++) se += expf(logits[c] - m);
        float lse = m + logf(se);
        for (int c = 0; c < NCLS; c++) out[c] = logits[c] - lse;
    }
}

extern "C" void kernel_launch(void* const* d_in, const int* in_sizes, int n_in,
                              void* d_out, int out_size) {
    const float* x    = (const float*)d_in[0];
    const int*   esrc = (const int*)d_in[1];
    const int*   edst = (const int*)d_in[2];
    const float* ew   = (const float*)d_in[3];
    const float* W1   = (const float*)d_in[4];
    const float* b1   = (const float*)d_in[5];
    const float* W2   = (const float*)d_in[6];
    const float* b2   = (const float*)d_in[7];
    const float* W3   = (const float*)d_in[8];
    const float* b3   = (const float*)d_in[9];
    const float* linW = (const float*)d_in[10];
    const float* linb = (const float*)d_in[11];
    float* out = (float*)d_out;

    int N = in_sizes[0] / DF;
    int E = in_sizes[1];

    static int attr_set = 0;
    if (!attr_set) {
        cudaFuncSetAttribute(gemm_kernel, cudaFuncAttributeMaxDynamicSharedMemorySize, GEMM_SMEM);
        attr_set = 1;
    }

    int eb = (E + 255) / 256;
    int gemm_blocks = ((N + 127) / 128) * 2;
    int seg_blocks = (N + 7) / 8;
    int scan_blocks = (N + 1 + SCB - 1) / SCB;

    // gemm1 sits in the ncu capture slot (4th kernel).
    prep_kernel<<<2048, 256>>>(x, W1, W2, W3, N);          // 1
    init_kernel<<<(N + 256) / 256, 256>>>(N);              // 2
    hist_kernel<<<eb, 256>>>(edst, E);                     // 3
    gemm_kernel<<<gemm_blocks, 256, GEMM_SMEM>>>(N, 0);    // 4 <- capture
    scan1_kernel<<<scan_blocks, SCB>>>(N);                 // 5
    scan2_kernel<<<1, SCB>>>();                            // 6
    scan3_kernel<<<scan_blocks, SCB>>>(N);                 // 7
    reorder_kernel<<<eb, 256>>>(esrc, edst, ew, E);        // 8

    seg_kernel<<<seg_blocks, 256>>>(b1, N, 0, 1);
    gemm_kernel<<<gemm_blocks, 256, GEMM_SMEM>>>(N, 1);
    seg_kernel<<<seg_blocks, 256>>>(b2, N, 1, 1);
    gemm_kernel<<<gemm_blocks, 256, GEMM_SMEM>>>(N, 2);
    seg_kernel<<<seg_blocks, 256>>>(b3, N, 2, 0);
    final_kernel<<<1, 128>>>(linW, linb, out);
}

// round 15
// speedup vs baseline: 1.9649x; 1.0296x over previous
#include <cuda_runtime.h>
#include <cuda_fp16.h>
#include <cuda_bf16.h>
#include <cstdint>

#define DF 128
#define NMAX 50000
#define EMAX 800000
#define NCLS 10
#define SCB 256
#define NSCB ((NMAX + 1 + SCB - 1) / SCB)

// Scratch (allocation-free __device__ globals).
__device__ __align__(16) __half g_support[(size_t)NMAX * DF];  // gemm out / seg in
__device__ __align__(16) __half g_ah[(size_t)NMAX * DF];       // fp16 activations (gemm A input)
__device__ __align__(16) __half g_w16[3 * DF * DF];            // fp16 weights
__device__ __align__(16) int2   g_edge_s[EMAX];
__device__ int g_cnt[NMAX + 1];
__device__ int g_rowptr[NMAX + 1];
__device__ int g_cur[NMAX + 1];
__device__ int g_blksum[NSCB];
__device__ int g_blkoff[NSCB];
__device__ unsigned g_okey[3 * DF];

__device__ __forceinline__ unsigned fenc(float x) {
    unsigned u = __float_as_uint(x);
    return (u & 0x80000000u) ? ~u : (u | 0x80000000u);
}
__device__ __forceinline__ float fdec(unsigned k) {
    unsigned u = (k & 0x80000000u) ? (k & 0x7FFFFFFFu) : ~k;
    return __uint_as_float(u);
}
__device__ __forceinline__ unsigned smem_u32(const void* p) {
    return (unsigned)__cvta_generic_to_shared(p);
}
__device__ __forceinline__ unsigned h2_as_u32(__half2 h) {
    return *reinterpret_cast<unsigned*>(&h);
}

// ---------------- prep: one-time fp32->fp16 conversion of x and W1/2/3 -----

__global__ __launch_bounds__(256) void prep_kernel(const float* __restrict__ x,
                                                   const float* __restrict__ W1,
                                                   const float* __restrict__ W2,
                                                   const float* __restrict__ W3,
                                                   int N) {
    long total = (long)N * 32;          // N*128 floats as float4
    for (long i = (long)blockIdx.x * 256 + threadIdx.x; i < total;
         i += (long)gridDim.x * 256) {
        float4 v = ((const float4*)x)[i];
        uint2 pk;
        pk.x = h2_as_u32(__floats2half2_rn(v.x, v.y));
        pk.y = h2_as_u32(__floats2half2_rn(v.z, v.w));
        ((uint2*)g_ah)[i] = pk;
    }
    for (int i = blockIdx.x * 256 + threadIdx.x; i < 3 * DF * 32;
         i += gridDim.x * 256) {
        const float* Wsrc = (i < DF * 32) ? W1 : (i < 2 * DF * 32) ? W2 : W3;
        int li = i & (DF * 32 - 1);
        float4 v = ((const float4*)Wsrc)[li];
        uint2 pk;
        pk.x = h2_as_u32(__floats2half2_rn(v.x, v.y));
        pk.y = h2_as_u32(__floats2half2_rn(v.z, v.w));
        ((uint2*)g_w16)[i] = pk;
    }
}

// ---------------- sort: counting sort of edges by dst -------------------

__global__ __launch_bounds__(256) void init_kernel(int N) {
    int i = blockIdx.x * 256 + threadIdx.x;
    if (i <= N) g_cnt[i] = 0;
    if (i < 3 * DF) g_okey[i] = 0u;
}

__global__ __launch_bounds__(256) void hist_kernel(const int* __restrict__ dst, int E) {
    int e = blockIdx.x * 256 + threadIdx.x;
    if (e < E) atomicAdd(&g_cnt[dst[e]], 1);
}

__global__ __launch_bounds__(SCB) void scan1_kernel(int N) {
    __shared__ int sh[SCB];
    int t = threadIdx.x;
    int idx = blockIdx.x * SCB + t;
    int v = (idx < N) ? g_cnt[idx] : 0;
    sh[t] = v;
    __syncthreads();
    for (int off = SCB / 2; off > 0; off >>= 1) {
        if (t < off) sh[t] += sh[t + off];
        __syncthreads();
    }
    if (t == 0) g_blksum[blockIdx.x] = sh[0];
}

__global__ __launch_bounds__(SCB) void scan2_kernel() {
    __shared__ int sh[SCB];
    int t = threadIdx.x;
    sh[t] = (t < NSCB) ? g_blksum[t] : 0;
    __syncthreads();
    for (int off = 1; off < SCB; off <<= 1) {
        int v = sh[t];
        int add = (t >= off) ? sh[t - off] : 0;
        __syncthreads();
        sh[t] = v + add;
        __syncthreads();
    }
    if (t < NSCB) g_blkoff[t] = (t == 0) ? 0 : sh[t - 1];
}

__global__ __launch_bounds__(SCB) void scan3_kernel(int N) {
    __shared__ int sh[SCB];
    int t = threadIdx.x;
    int idx = blockIdx.x * SCB + t;
    int v = (idx < N) ? g_cnt[idx] : 0;
    sh[t] = v;
    __syncthreads();
    for (int off = 1; off < SCB; off <<= 1) {
        int x = sh[t];
        int add = (t >= off) ? sh[t - off] : 0;
        __syncthreads();
        sh[t] = x + add;
        __syncthreads();
    }
    if (idx <= N) {
        int excl = g_blkoff[blockIdx.x] + sh[t] - v;
        g_rowptr[idx] = excl;
        if (idx < N) g_cur[idx] = excl;
    }
}

__global__ __launch_bounds__(256) void reorder_kernel(const int* __restrict__ src,
                                                      const int* __restrict__ dst,
                                                      const float* __restrict__ w,
                                                      int E) {
    int e = blockIdx.x * 256 + threadIdx.x;
    if (e >= E) return;
    int d = dst[e];
    int pos = atomicAdd(&g_cur[d], 1);
    g_edge_s[pos] = make_int2(src[e], __float_as_int(w[e]));
}

// ---------------- GEMM: support(fp16) = g_ah(fp16) @ g_w16[layer] ----------
// Block tile 128(m) x 64(n); 8 warps, warp tile 32x32 = 2(m) x 4(n) m16n8k16.

#define SA 136   // A smem stride (halves)
#define SW 72    // W smem stride (halves)
#define GEMM_SMEM ((DF * SA + DF * SW) * (int)sizeof(__half))  // 53248 B

__global__ __launch_bounds__(256, 3) void gemm_kernel(int N, int layer) {
    extern __shared__ __half smem_h[];
    __half* As = smem_h;             // [128 m][136] (k)
    __half* Ws = smem_h + DF * SA;   // [128 k][72] (n half)

    int t = threadIdx.x;
    int lane = t & 31;
    int wrp = t >> 5;
    int wm = wrp & 3;
    int wn = wrp >> 2;
    int rb = blockIdx.x >> 1;
    int nh = blockIdx.x & 1;
    int r0 = rb * 128;

    const __half* Wg = g_w16 + layer * DF * DF;

    for (int i = t; i < DF * 16; i += 256) {
        int row = i >> 4;
        int sg = (i & 15) * 8;
        int gr = r0 + row;
        uint4 v = make_uint4(0u, 0u, 0u, 0u);
        if (gr < N) v = *(const uint4*)&g_ah[(size_t)gr * DF + sg];
        *(uint4*)&As[row * SA + sg] = v;
    }
    for (int i = t; i < DF * 8; i += 256) {
        int k = i >> 3;
        int sg = (i & 7) * 8;
        uint4 v = *(const uint4*)&Wg[k * DF + nh * 64 + sg];
        *(uint4*)&Ws[k * SW + sg] = v;
    }
    __syncthreads();

    float acc[2][4][4];
#pragma unroll
    for (int mt = 0; mt < 2; mt++)
#pragma unroll
        for (int nt = 0; nt < 4; nt++)
#pragma unroll
            for (int r = 0; r < 4; r++) acc[mt][nt][r] = 0.f;

    int gid = lane >> 2;
    int tig = lane & 3;
    int tr = lane & 7;
    int tile = lane >> 3;
    int row_off = (tile & 1) ? 8 : 0;
    int col_off = (tile & 2) ? 8 : 0;

    unsigned addrA[2];
#pragma unroll
    for (int mt = 0; mt < 2; mt++) {
        int m0 = wm * 32 + mt * 16;
        addrA[mt] = smem_u32(&As[(m0 + tr + row_off) * SA + col_off]);
    }
    unsigned addrB[2];
#pragma unroll
    for (int np = 0; np < 2; np++) {
        int nb = wn * 32 + np * 16;
        addrB[np] = smem_u32(&Ws[(tr + row_off) * SW + nb + col_off]);
    }

#pragma unroll
    for (int ks = 0; ks < 8; ks++) {
        unsigned af[2][4];
#pragma unroll
        for (int mt = 0; mt < 2; mt++) {
            asm volatile(
                "ldmatrix.sync.aligned.m8n8.x4.shared.b16 {%0,%1,%2,%3}, [%4];"
                : "=r"(af[mt][0]), "=r"(af[mt][1]), "=r"(af[mt][2]), "=r"(af[mt][3])
                : "r"(addrA[mt] + ks * 16 * (unsigned)sizeof(__half)));
        }
        unsigned bf[2][4];
#pragma unroll
        for (int np = 0; np < 2; np++) {
            asm volatile(
                "ldmatrix.sync.aligned.m8n8.x4.trans.shared.b16 {%0,%1,%2,%3}, [%4];"
                : "=r"(bf[np][0]), "=r"(bf[np][1]), "=r"(bf[np][2]), "=r"(bf[np][3])
                : "r"(addrB[np] + ks * 16 * SW * (unsigned)sizeof(__half)));
        }
#pragma unroll
        for (int np = 0; np < 2; np++) {
#pragma unroll
            for (int sub = 0; sub < 2; sub++) {
                int nt = np * 2 + sub;
#pragma unroll
                for (int mt = 0; mt < 2; mt++) {
                    asm volatile(
                        "mma.sync.aligned.m16n8k16.row.col.f32.f16.f16.f32 "
                        "{%0,%1,%2,%3}, {%4,%5,%6,%7}, {%8,%9}, {%0,%1,%2,%3};"
                        : "+f"(acc[mt][nt][0]), "+f"(acc[mt][nt][1]),
                          "+f"(acc[mt][nt][2]), "+f"(acc[mt][nt][3])
                        : "r"(af[mt][0]), "r"(af[mt][1]),
                          "r"(af[mt][2]), "r"(af[mt][3]),
                        "r"(bf[np][sub * 2]), "r"(bf[np][sub * 2 + 1]));
                }
            }
        }
    }

#pragma unroll
    for (int mt = 0; mt < 2; mt++) {
#pragma unroll
        for (int nt = 0; nt < 4; nt++) {
            int row = r0 + wm * 32 + mt * 16 + gid;
            int col = nh * 64 + wn * 32 + nt * 8 + 2 * tig;
            if (row < N)
                *(__half2*)&g_support[(size_t)row * DF + col] =
                    __floats2half2_rn(acc[mt][nt][0], acc[mt][nt][1]);
            if (row + 8 < N)
                *(__half2*)&g_support[(size_t)(row + 8) * DF + col] =
                    __floats2half2_rn(acc[mt][nt][2], acc[mt][nt][3]);
        }
    }
}

// ---------------- segment-sum + bias (+relu, fp16 h write) + column max ----

__device__ __forceinline__ void edge_fma(float4& a, const uint2 u, const float w) {
    float2 lo = __half22float2(*(const __half2*)&u.x);
    float2 hi = __half22float2(*(const __half2*)&u.y);
    a.x += lo.x * w; a.y += lo.y * w;
    a.z += hi.x * w; a.w += hi.y * w;
}

__global__ __launch_bounds__(256) void seg_kernel(const float* __restrict__ b,
                                                  int N, int layer, int do_relu) {
    __shared__ unsigned smax[DF];
    int t = threadIdx.x;
    int lane = t & 31;
    int wrp = t >> 5;
    if (t < DF) smax[t] = 0u;
    __syncthreads();

    int d = blockIdx.x * 8 + wrp;
    if (d < N) {
        int beg = g_rowptr[d];
        int end = g_rowptr[d + 1];
        const uint2* sup = (const uint2*)g_support;

        float4 acc0 = make_float4(0.f, 0.f, 0.f, 0.f);
        float4 acc1 = make_float4(0.f, 0.f, 0.f, 0.f);

        for (int base = beg; base < end; base += 32) {
            int m = end - base;
            if (m > 32) m = 32;
            int2 dsc = make_int2(0, 0);
            if (lane < m) dsc = g_edge_s[base + lane];

            int j = 0;
            for (; j + 8 <= m; j += 8) {
                int s0 = __shfl_sync(0xffffffffu, dsc.x, j + 0);
                int s1 = __shfl_sync(0xffffffffu, dsc.x, j + 1);
                int s2 = __shfl_sync(0xffffffffu, dsc.x, j + 2);
                int s3 = __shfl_sync(0xffffffffu, dsc.x, j + 3);
                int s4 = __shfl_sync(0xffffffffu, dsc.x, j + 4);
                int s5 = __shfl_sync(0xffffffffu, dsc.x, j + 5);
                int s6 = __shfl_sync(0xffffffffu, dsc.x, j + 6);
                int s7 = __shfl_sync(0xffffffffu, dsc.x, j + 7);
                float w0 = __int_as_float(__shfl_sync(0xffffffffu, dsc.y, j + 0));
                float w1 = __int_as_float(__shfl_sync(0xffffffffu, dsc.y, j + 1));
                float w2 = __int_as_float(__shfl_sync(0xffffffffu, dsc.y, j + 2));
                float w3 = __int_as_float(__shfl_sync(0xffffffffu, dsc.y, j + 3));
                float w4 = __int_as_float(__shfl_sync(0xffffffffu, dsc.y, j + 4));
                float w5 = __int_as_float(__shfl_sync(0xffffffffu, dsc.y, j + 5));
                float w6 = __int_as_float(__shfl_sync(0xffffffffu, dsc.y, j + 6));
                float w7 = __int_as_float(__shfl_sync(0xffffffffu, dsc.y, j + 7));
                uint2 u0 = sup[(size_t)s0 * 32 + lane];
                uint2 u1 = sup[(size_t)s1 * 32 + lane];
                uint2 u2 = sup[(size_t)s2 * 32 + lane];
                uint2 u3 = sup[(size_t)s3 * 32 + lane];
                uint2 u4 = sup[(size_t)s4 * 32 + lane];
                uint2 u5 = sup[(size_t)s5 * 32 + lane];
                uint2 u6 = sup[(size_t)s6 * 32 + lane];
                uint2 u7 = sup[(size_t)s7 * 32 + lane];
                edge_fma(acc0, u0, w0);
                edge_fma(acc1, u1, w1);
                edge_fma(acc0, u2, w2);
                edge_fma(acc1, u3, w3);
                edge_fma(acc0, u4, w4);
                edge_fma(acc1, u5, w5);
                edge_fma(acc0, u6, w6);
                edge_fma(acc1, u7, w7);
            }
            for (; j + 2 <= m; j += 2) {
                int s0 = __shfl_sync(0xffffffffu, dsc.x, j + 0);
                int s1 = __shfl_sync(0xffffffffu, dsc.x, j + 1);
                float w0 = __int_as_float(__shfl_sync(0xffffffffu, dsc.y, j + 0));
                float w1 = __int_as_float(__shfl_sync(0xffffffffu, dsc.y, j + 1));
                uint2 u0 = sup[(size_t)s0 * 32 + lane];
                uint2 u1 = sup[(size_t)s1 * 32 + lane];
                edge_fma(acc0, u0, w0);
                edge_fma(acc1, u1, w1);
            }
            if (j < m) {
                int s0 = __shfl_sync(0xffffffffu, dsc.x, j);
                float w0 = __int_as_float(__shfl_sync(0xffffffffu, dsc.y, j));
                uint2 u0 = sup[(size_t)s0 * 32 + lane];
                edge_fma(acc0, u0, w0);
            }
        }

        float4 v;
        const float4* bb = (const float4*)b;
        float4 bv = bb[lane];
        v.x = acc0.x + acc1.x + bv.x;
        v.y = acc0.y + acc1.y + bv.y;
        v.z = acc0.z + acc1.z + bv.z;
        v.w = acc0.w + acc1.w + bv.w;
        if (do_relu) {
            v.x = fmaxf(v.x, 0.f); v.y = fmaxf(v.y, 0.f);
            v.z = fmaxf(v.z, 0.f); v.w = fmaxf(v.w, 0.f);
            uint2 pk;
            pk.x = h2_as_u32(__floats2half2_rn(v.x, v.y));
            pk.y = h2_as_u32(__floats2half2_rn(v.z, v.w));
            *(uint2*)&g_ah[(size_t)d * DF + lane * 4] = pk;
        }
        atomicMax(&smax[lane * 4 + 0], fenc(v.x));
        atomicMax(&smax[lane * 4 + 1], fenc(v.y));
        atomicMax(&smax[lane * 4 + 2], fenc(v.z));
        atomicMax(&smax[lane * 4 + 3], fenc(v.w));
    }
    __syncthreads();
    if (t < DF) atomicMax(&g_okey[layer * DF + t], smax[t]);
}

// ---------------- head ----------------------------------------------------

__global__ __launch_bounds__(128) void final_kernel(const float* __restrict__ lin_W,
                                                    const float* __restrict__ lin_b,
                                                    float* __restrict__ out) {
    __shared__ float lin_in[3 * DF];
    __shared__ float logits[NCLS];
    int t = threadIdx.x;
    for (int i = t; i < 3 * DF; i += 128) lin_in[i] = fdec(g_okey[i]);
    __syncthreads();
    if (t < NCLS) {
        float s = lin_b[t];
#pragma unroll 4
        for (int j = 0; j < 3 * DF; j++) s += lin_W[t * 3 * DF + j] * lin_in[j];
        logits[t] = s;
    }
    __syncthreads();
    if (t == 0) {
        float m = -3.402823466e+38f;
        for (int c = 0; c < NCLS; c++) m = fmaxf(m, logits[c]);
        float se = 0.f;
        for (int c = 0; c < NCLS; c++) se += expf(logits[c] - m);
        float lse = m + logf(se);
        for (int c = 0; c < NCLS; c++) out[c] = logits[c] - lse;
    }
}

extern "C" void kernel_launch(void* const* d_in, const int* in_sizes, int n_in,
                              void* d_out, int out_size) {
    const float* x    = (const float*)d_in[0];
    const int*   esrc = (const int*)d_in[1];
    const int*   edst = (const int*)d_in[2];
    const float* ew   = (const float*)d_in[3];
    const float* W1   = (const float*)d_in[4];
    const float* b1   = (const float*)d_in[5];
    const float* W2   = (const float*)d_in[6];
    const float* b2   = (const float*)d_in[7];
    const float* W3   = (const float*)d_in[8];
    const float* b3   = (const float*)d_in[9];
    const float* linW = (const float*)d_in[10];
    const float* linb = (const float*)d_in[11];
    float* out = (float*)d_out;

    int N = in_sizes[0] / DF;
    int E = in_sizes[1];

    static cudaStream_t s2;
    static cudaEvent_t ev_fork, ev_join;
    static int inited = 0;
    if (!inited) {
        cudaFuncSetAttribute(gemm_kernel, cudaFuncAttributeMaxDynamicSharedMemorySize, GEMM_SMEM);
        cudaStreamCreateWithFlags(&s2, cudaStreamNonBlocking);
        cudaEventCreateWithFlags(&ev_fork, cudaEventDisableTiming);
        cudaEventCreateWithFlags(&ev_join, cudaEventDisableTiming);
        inited = 1;
    }

    int eb = (E + 255) / 256;
    int gemm_blocks = ((N + 127) / 128) * 2;
    int seg_blocks = (N + 7) / 8;
    int scan_blocks = (N + 1 + SCB - 1) / SCB;

    // Fork: sort chain on side stream, prep+gemm1 on main (capture) stream.
    cudaEventRecord(ev_fork, 0);
    cudaStreamWaitEvent(s2, ev_fork, 0);

    prep_kernel<<<2048, 256>>>(x, W1, W2, W3, N);               // main 1
    init_kernel<<<(N + 256) / 256, 256, 0, s2>>>(N);            // side 2
    hist_kernel<<<eb, 256, 0, s2>>>(edst, E);                   // side 3
    gemm_kernel<<<gemm_blocks, 256, GEMM_SMEM>>>(N, 0);         // main 4 <- capture slot
    scan1_kernel<<<scan_blocks, SCB, 0, s2>>>(N);               // side 5
    scan2_kernel<<<1, SCB, 0, s2>>>();                          // side 6
    scan3_kernel<<<scan_blocks, SCB, 0, s2>>>(N);               // side 7
    reorder_kernel<<<eb, 256, 0, s2>>>(esrc, edst, ew, E);      // side 8

    // Join: seg1 needs both gemm1 (main) and reorder (side).
    cudaEventRecord(ev_join, s2);
    cudaStreamWaitEvent(0, ev_join, 0);

    seg_kernel<<<seg_blocks, 256>>>(b1, N, 0, 1);
    gemm_kernel<<<gemm_blocks, 256, GEMM_SMEM>>>(N, 1);
    seg_kernel<<<seg_blocks, 256>>>(b2, N, 1, 1);
    gemm_kernel<<<gemm_blocks, 256, GEMM_SMEM>>>(N, 2);
    seg_kernel<<<seg_blocks, 256>>>(b3, N, 2, 0);
    final_kernel<<<1, 128>>>(linW, linb, out);
}

// round 16
// speedup vs baseline: 1.9680x; 1.0016x over previous
#include <cuda_runtime.h>
#include <cuda_fp16.h>
#include <cuda_bf16.h>
#include <cstdint>

#define DF 128
#define NMAX 50000
#define EMAX 800000
#define NCLS 10
#define SCB 256
#define NSCB ((NMAX + 1 + SCB - 1) / SCB)

// Scratch (allocation-free __device__ globals).
__device__ __align__(16) __half g_support[(size_t)NMAX * DF];  // gemm out / seg in
__device__ __align__(16) __half g_ah[(size_t)NMAX * DF];       // fp16 activations (gemm A input)
__device__ __align__(16) __half g_w16[3 * DF * DF];            // fp16 weights
__device__ __align__(16) int2   g_edge_s[EMAX];
__device__ int g_cnt[NMAX + 1];
__device__ int g_rowptr[NMAX + 1];
__device__ int g_cur[NMAX + 1];
__device__ int g_blksum[NSCB];
__device__ int g_blkoff[NSCB];
__device__ unsigned g_okey[3 * DF];

__device__ __forceinline__ unsigned fenc(float x) {
    unsigned u = __float_as_uint(x);
    return (u & 0x80000000u) ? ~u : (u | 0x80000000u);
}
__device__ __forceinline__ float fdec(unsigned k) {
    unsigned u = (k & 0x80000000u) ? (k & 0x7FFFFFFFu) : ~k;
    return __uint_as_float(u);
}
__device__ __forceinline__ unsigned smem_u32(const void* p) {
    return (unsigned)__cvta_generic_to_shared(p);
}
__device__ __forceinline__ unsigned h2_as_u32(__half2 h) {
    return *reinterpret_cast<unsigned*>(&h);
}
#define CP_ASYNC16(sm, gp) \
    asm volatile("cp.async.cg.shared.global [%0], [%1], 16;" :: "r"(sm), "l"(gp))
#define CP_ASYNC_WAIT_ALL() \
    asm volatile("cp.async.commit_group;\ncp.async.wait_group 0;" ::: "memory")

// ---------------- prep: one-time fp32->fp16 conversion of x and W1/2/3 -----

__global__ __launch_bounds__(256) void prep_kernel(const float* __restrict__ x,
                                                   const float* __restrict__ W1,
                                                   const float* __restrict__ W2,
                                                   const float* __restrict__ W3,
                                                   int N) {
    long total = (long)N * 32;
    for (long i = (long)blockIdx.x * 256 + threadIdx.x; i < total;
         i += (long)gridDim.x * 256) {
        float4 v = ((const float4*)x)[i];
        uint2 pk;
        pk.x = h2_as_u32(__floats2half2_rn(v.x, v.y));
        pk.y = h2_as_u32(__floats2half2_rn(v.z, v.w));
        ((uint2*)g_ah)[i] = pk;
    }
    for (int i = blockIdx.x * 256 + threadIdx.x; i < 3 * DF * 32;
         i += gridDim.x * 256) {
        const float* Wsrc = (i < DF * 32) ? W1 : (i < 2 * DF * 32) ? W2 : W3;
        int li = i & (DF * 32 - 1);
        float4 v = ((const float4*)Wsrc)[li];
        uint2 pk;
        pk.x = h2_as_u32(__floats2half2_rn(v.x, v.y));
        pk.y = h2_as_u32(__floats2half2_rn(v.z, v.w));
        ((uint2*)g_w16)[i] = pk;
    }
}

// ---------------- sort: counting sort of edges by dst -------------------

__global__ __launch_bounds__(256) void init_kernel(int N) {
    int i = blockIdx.x * 256 + threadIdx.x;
    if (i <= N) g_cnt[i] = 0;
    if (i < 3 * DF) g_okey[i] = 0u;
}

__global__ __launch_bounds__(256) void hist_kernel(const int* __restrict__ dst, int E) {
    int e = blockIdx.x * 256 + threadIdx.x;
    if (e < E) atomicAdd(&g_cnt[dst[e]], 1);
}

__global__ __launch_bounds__(SCB) void scan1_kernel(int N) {
    __shared__ int sh[SCB];
    int t = threadIdx.x;
    int idx = blockIdx.x * SCB + t;
    int v = (idx < N) ? g_cnt[idx] : 0;
    sh[t] = v;
    __syncthreads();
    for (int off = SCB / 2; off > 0; off >>= 1) {
        if (t < off) sh[t] += sh[t + off];
        __syncthreads();
    }
    if (t == 0) g_blksum[blockIdx.x] = sh[0];
}

__global__ __launch_bounds__(SCB) void scan2_kernel() {
    __shared__ int sh[SCB];
    int t = threadIdx.x;
    sh[t] = (t < NSCB) ? g_blksum[t] : 0;
    __syncthreads();
    for (int off = 1; off < SCB; off <<= 1) {
        int v = sh[t];
        int add = (t >= off) ? sh[t - off] : 0;
        __syncthreads();
        sh[t] = v + add;
        __syncthreads();
    }
    if (t < NSCB) g_blkoff[t] = (t == 0) ? 0 : sh[t - 1];
}

__global__ __launch_bounds__(SCB) void scan3_kernel(int N) {
    __shared__ int sh[SCB];
    int t = threadIdx.x;
    int idx = blockIdx.x * SCB + t;
    int v = (idx < N) ? g_cnt[idx] : 0;
    sh[t] = v;
    __syncthreads();
    for (int off = 1; off < SCB; off <<= 1) {
        int x = sh[t];
        int add = (t >= off) ? sh[t - off] : 0;
        __syncthreads();
        sh[t] = x + add;
        __syncthreads();
    }
    if (idx <= N) {
        int excl = g_blkoff[blockIdx.x] + sh[t] - v;
        g_rowptr[idx] = excl;
        if (idx < N) g_cur[idx] = excl;
    }
}

__global__ __launch_bounds__(256) void reorder_kernel(const int* __restrict__ src,
                                                      const int* __restrict__ dst,
                                                      const float* __restrict__ w,
                                                      int E) {
    int e = blockIdx.x * 256 + threadIdx.x;
    if (e >= E) return;
    int d = dst[e];
    int pos = atomicAdd(&g_cur[d], 1);
    g_edge_s[pos] = make_int2(src[e], __float_as_int(w[e]));
}

// ---------------- GEMM: support(fp16) = g_ah(fp16) @ g_w16[layer] ----------
// Block tile 128(m) x 128(n); 8 warps 4(m)x2(n), warp tile 32x64 =
// 2(m) x 8(n) m16n8k16. cp.async fp16 staging (no conversions). 2 CTAs/SM.

#define SH 136   // smem stride in halves (both tiles)
#define GEMM_SMEM (2 * DF * SH * (int)sizeof(__half))  // 69632 B

__global__ __launch_bounds__(256, 2) void gemm_kernel(int N, int layer) {
    extern __shared__ __half smem_h[];
    __half* As = smem_h;             // [128 m][136] (k)
    __half* Ws = smem_h + DF * SH;   // [128 k][136] (n)

    int t = threadIdx.x;
    int lane = t & 31;
    int wrp = t >> 5;
    int wm = wrp >> 1;
    int wn = wrp & 1;
    int r0 = blockIdx.x * 128;

    const __half* Wg = g_w16 + layer * DF * DF;

    // Stage A [128 m][128 k] fp16 via cp.async: 16 x 16B chunks per row.
    for (int i = t; i < DF * 16; i += 256) {
        int row = i >> 4;
        int sg = (i & 15) * 8;
        int gr = r0 + row;
        if (gr < N) {
            CP_ASYNC16(smem_u32(&As[row * SH + sg]), &g_ah[(size_t)gr * DF + sg]);
        } else {
            *(uint4*)&As[row * SH + sg] = make_uint4(0u, 0u, 0u, 0u);
        }
    }
    // Stage W [128 k][128 n] fp16 via cp.async.
    for (int i = t; i < DF * 16; i += 256) {
        int k = i >> 4;
        int sg = (i & 15) * 8;
        CP_ASYNC16(smem_u32(&Ws[k * SH + sg]), &Wg[k * DF + sg]);
    }
    CP_ASYNC_WAIT_ALL();
    __syncthreads();

    float acc[2][8][4];
#pragma unroll
    for (int mt = 0; mt < 2; mt++)
#pragma unroll
        for (int nt = 0; nt < 8; nt++)
#pragma unroll
            for (int r = 0; r < 4; r++) acc[mt][nt][r] = 0.f;

    int gid = lane >> 2;
    int tig = lane & 3;
    int tr = lane & 7;
    int tile = lane >> 3;
    int row_off = (tile & 1) ? 8 : 0;
    int col_off = (tile & 2) ? 8 : 0;

    unsigned addrA[2];
#pragma unroll
    for (int mt = 0; mt < 2; mt++) {
        int m0 = wm * 32 + mt * 16;
        addrA[mt] = smem_u32(&As[(m0 + tr + row_off) * SH + col_off]);
    }
    unsigned addrB[4];
#pragma unroll
    for (int np = 0; np < 4; np++) {
        int nb = wn * 64 + np * 16;
        addrB[np] = smem_u32(&Ws[(tr + row_off) * SH + nb + col_off]);
    }

#pragma unroll
    for (int ks = 0; ks < 8; ks++) {
        unsigned af[2][4];
#pragma unroll
        for (int mt = 0; mt < 2; mt++) {
            asm volatile(
                "ldmatrix.sync.aligned.m8n8.x4.shared.b16 {%0,%1,%2,%3}, [%4];"
                : "=r"(af[mt][0]), "=r"(af[mt][1]), "=r"(af[mt][2]), "=r"(af[mt][3])
                : "r"(addrA[mt] + ks * 16 * (unsigned)sizeof(__half)));
        }
        unsigned bf[4][4];
#pragma unroll
        for (int np = 0; np < 4; np++) {
            asm volatile(
                "ldmatrix.sync.aligned.m8n8.x4.trans.shared.b16 {%0,%1,%2,%3}, [%4];"
                : "=r"(bf[np][0]), "=r"(bf[np][1]), "=r"(bf[np][2]), "=r"(bf[np][3])
                : "r"(addrB[np] + ks * 16 * SH * (unsigned)sizeof(__half)));
        }
#pragma unroll
        for (int np = 0; np < 4; np++) {
#pragma unroll
            for (int sub = 0; sub < 2; sub++) {
                int nt = np * 2 + sub;
#pragma unroll
                for (int mt = 0; mt < 2; mt++) {
                    asm volatile(
                        "mma.sync.aligned.m16n8k16.row.col.f32.f16.f16.f32 "
                        "{%0,%1,%2,%3}, {%4,%5,%6,%7}, {%8,%9}, {%0,%1,%2,%3};"
                        : "+f"(acc[mt][nt][0]), "+f"(acc[mt][nt][1]),
                          "+f"(acc[mt][nt][2]), "+f"(acc[mt][nt][3])
                        : "r"(af[mt][0]), "r"(af[mt][1]),
                          "r"(af[mt][2]), "r"(af[mt][3]),
                        "r"(bf[np][sub * 2]), "r"(bf[np][sub * 2 + 1]));
                }
            }
        }
    }

#pragma unroll
    for (int mt = 0; mt < 2; mt++) {
#pragma unroll
        for (int nt = 0; nt < 8; nt++) {
            int row = r0 + wm * 32 + mt * 16 + gid;
            int col = wn * 64 + nt * 8 + 2 * tig;
            if (row < N)
                *(__half2*)&g_support[(size_t)row * DF + col] =
                    __floats2half2_rn(acc[mt][nt][0], acc[mt][nt][1]);
            if (row + 8 < N)
                *(__half2*)&g_support[(size_t)(row + 8) * DF + col] =
                    __floats2half2_rn(acc[mt][nt][2], acc[mt][nt][3]);
        }
    }
}

// ---------------- segment-sum + bias (+relu, fp16 h write) + column max ----

__device__ __forceinline__ void edge_fma(float4& a, const uint2 u, const float w) {
    float2 lo = __half22float2(*(const __half2*)&u.x);
    float2 hi = __half22float2(*(const __half2*)&u.y);
    a.x += lo.x * w; a.y += lo.y * w;
    a.z += hi.x * w; a.w += hi.y * w;
}

__global__ __launch_bounds__(256) void seg_kernel(const float* __restrict__ b,
                                                  int N, int layer, int do_relu) {
    __shared__ unsigned smax[DF];
    int t = threadIdx.x;
    int lane = t & 31;
    int wrp = t >> 5;
    if (t < DF) smax[t] = 0u;
    __syncthreads();

    int d = blockIdx.x * 8 + wrp;
    if (d < N) {
        int beg = g_rowptr[d];
        int end = g_rowptr[d + 1];
        const uint2* sup = (const uint2*)g_support;

        float4 acc0 = make_float4(0.f, 0.f, 0.f, 0.f);
        float4 acc1 = make_float4(0.f, 0.f, 0.f, 0.f);

        for (int base = beg; base < end; base += 32) {
            int m = end - base;
            if (m > 32) m = 32;
            int2 dsc = make_int2(0, 0);
            if (lane < m) dsc = g_edge_s[base + lane];

            int j = 0;
            for (; j + 8 <= m; j += 8) {
                int s0 = __shfl_sync(0xffffffffu, dsc.x, j + 0);
                int s1 = __shfl_sync(0xffffffffu, dsc.x, j + 1);
                int s2 = __shfl_sync(0xffffffffu, dsc.x, j + 2);
                int s3 = __shfl_sync(0xffffffffu, dsc.x, j + 3);
                int s4 = __shfl_sync(0xffffffffu, dsc.x, j + 4);
                int s5 = __shfl_sync(0xffffffffu, dsc.x, j + 5);
                int s6 = __shfl_sync(0xffffffffu, dsc.x, j + 6);
                int s7 = __shfl_sync(0xffffffffu, dsc.x, j + 7);
                float w0 = __int_as_float(__shfl_sync(0xffffffffu, dsc.y, j + 0));
                float w1 = __int_as_float(__shfl_sync(0xffffffffu, dsc.y, j + 1));
                float w2 = __int_as_float(__shfl_sync(0xffffffffu, dsc.y, j + 2));
                float w3 = __int_as_float(__shfl_sync(0xffffffffu, dsc.y, j + 3));
                float w4 = __int_as_float(__shfl_sync(0xffffffffu, dsc.y, j + 4));
                float w5 = __int_as_float(__shfl_sync(0xffffffffu, dsc.y, j + 5));
                float w6 = __int_as_float(__shfl_sync(0xffffffffu, dsc.y, j + 6));
                float w7 = __int_as_float(__shfl_sync(0xffffffffu, dsc.y, j + 7));
                uint2 u0 = sup[(size_t)s0 * 32 + lane];
                uint2 u1 = sup[(size_t)s1 * 32 + lane];
                uint2 u2 = sup[(size_t)s2 * 32 + lane];
                uint2 u3 = sup[(size_t)s3 * 32 + lane];
                uint2 u4 = sup[(size_t)s4 * 32 + lane];
                uint2 u5 = sup[(size_t)s5 * 32 + lane];
                uint2 u6 = sup[(size_t)s6 * 32 + lane];
                uint2 u7 = sup[(size_t)s7 * 32 + lane];
                edge_fma(acc0, u0, w0);
                edge_fma(acc1, u1, w1);
                edge_fma(acc0, u2, w2);
                edge_fma(acc1, u3, w3);
                edge_fma(acc0, u4, w4);
                edge_fma(acc1, u5, w5);
                edge_fma(acc0, u6, w6);
                edge_fma(acc1, u7, w7);
            }
            for (; j + 2 <= m; j += 2) {
                int s0 = __shfl_sync(0xffffffffu, dsc.x, j + 0);
                int s1 = __shfl_sync(0xffffffffu, dsc.x, j + 1);
                float w0 = __int_as_float(__shfl_sync(0xffffffffu, dsc.y, j + 0));
                float w1 = __int_as_float(__shfl_sync(0xffffffffu, dsc.y, j + 1));
                uint2 u0 = sup[(size_t)s0 * 32 + lane];
                uint2 u1 = sup[(size_t)s1 * 32 + lane];
                edge_fma(acc0, u0, w0);
                edge_fma(acc1, u1, w1);
            }
            if (j < m) {
                int s0 = __shfl_sync(0xffffffffu, dsc.x, j);
                float w0 = __int_as_float(__shfl_sync(0xffffffffu, dsc.y, j));
                uint2 u0 = sup[(size_t)s0 * 32 + lane];
                edge_fma(acc0, u0, w0);
            }
        }

        float4 v;
        const float4* bb = (const float4*)b;
        float4 bv = bb[lane];
        v.x = acc0.x + acc1.x + bv.x;
        v.y = acc0.y + acc1.y + bv.y;
        v.z = acc0.z + acc1.z + bv.z;
        v.w = acc0.w + acc1.w + bv.w;
        if (do_relu) {
            v.x = fmaxf(v.x, 0.f); v.y = fmaxf(v.y, 0.f);
            v.z = fmaxf(v.z, 0.f); v.w = fmaxf(v.w, 0.f);
            uint2 pk;
            pk.x = h2_as_u32(__floats2half2_rn(v.x, v.y));
            pk.y = h2_as_u32(__floats2half2_rn(v.z, v.w));
            *(uint2*)&g_ah[(size_t)d * DF + lane * 4] = pk;
        }
        atomicMax(&smax[lane * 4 + 0], fenc(v.x));
        atomicMax(&smax[lane * 4 + 1], fenc(v.y));
        atomicMax(&smax[lane * 4 + 2], fenc(v.z));
        atomicMax(&smax[lane * 4 + 3], fenc(v.w));
    }
    __syncthreads();
    if (t < DF) atomicMax(&g_okey[layer * DF + t], smax[t]);
}

// ---------------- head ----------------------------------------------------

__global__ __launch_bounds__(128) void final_kernel(const float* __restrict__ lin_W,
                                                    const float* __restrict__ lin_b,
                                                    float* __restrict__ out) {
    __shared__ float lin_in[3 * DF];
    __shared__ float logits[NCLS];
    int t = threadIdx.x;
    for (int i = t; i < 3 * DF; i += 128) lin_in[i] = fdec(g_okey[i]);
    __syncthreads();
    if (t < NCLS) {
        float s = lin_b[t];
#pragma unroll 4
        for (int j = 0; j < 3 * DF; j++) s += lin_W[t * 3 * DF + j] * lin_in[j];
        logits[t] = s;
    }
    __syncthreads();
    if (t == 0) {
        float m = -3.402823466e+38f;
        for (int c = 0; c < NCLS; c++) m = fmaxf(m, logits[c]);
        float se = 0.f;
        for (int c = 0; c < NCLS; c++) se += expf(logits[c] - m);
        float lse = m + logf(se);
        for (int c = 0; c < NCLS; c++) out[c] = logits[c] - lse;
    }
}

extern "C" void kernel_launch(void* const* d_in, const int* in_sizes, int n_in,
                              void* d_out, int out_size) {
    const float* x    = (const float*)d_in[0];
    const int*   esrc = (const int*)d_in[1];
    const int*   edst = (const int*)d_in[2];
    const float* ew   = (const float*)d_in[3];
    const float* W1   = (const float*)d_in[4];
    const float* b1   = (const float*)d_in[5];
    const float* W2   = (const float*)d_in[6];
    const float* b2   = (const float*)d_in[7];
    const float* W3   = (const float*)d_in[8];
    const float* b3   = (const float*)d_in[9];
    const float* linW = (const float*)d_in[10];
    const float* linb = (const float*)d_in[11];
    float* out = (float*)d_out;

    int N = in_sizes[0] / DF;
    int E = in_sizes[1];

    static cudaStream_t s2;
    static cudaEvent_t ev_fork, ev_join;
    static int inited = 0;
    if (!inited) {
        cudaFuncSetAttribute(gemm_kernel, cudaFuncAttributeMaxDynamicSharedMemorySize, GEMM_SMEM);
        cudaStreamCreateWithFlags(&s2, cudaStreamNonBlocking);
        cudaEventCreateWithFlags(&ev_fork, cudaEventDisableTiming);
        cudaEventCreateWithFlags(&ev_join, cudaEventDisableTiming);
        inited = 1;
    }

    int eb = (E + 255) / 256;
    int gemm_blocks = (N + 127) / 128;
    int seg_blocks = (N + 7) / 8;
    int scan_blocks = (N + 1 + SCB - 1) / SCB;

    // Fork: sort chain on side stream, prep+gemm1 on main (capture) stream.
    cudaEventRecord(ev_fork, 0);
    cudaStreamWaitEvent(s2, ev_fork, 0);

    prep_kernel<<<2048, 256>>>(x, W1, W2, W3, N);               // main 1
    init_kernel<<<(N + 256) / 256, 256, 0, s2>>>(N);            // side 2
    hist_kernel<<<eb, 256, 0, s2>>>(edst, E);                   // side 3
    gemm_kernel<<<gemm_blocks, 256, GEMM_SMEM>>>(N, 0);         // main 4 <- capture slot
    scan1_kernel<<<scan_blocks, SCB, 0, s2>>>(N);               // side 5
    scan2_kernel<<<1, SCB, 0, s2>>>();                          // side 6
    scan3_kernel<<<scan_blocks, SCB, 0, s2>>>(N);               // side 7
    reorder_kernel<<<eb, 256, 0, s2>>>(esrc, edst, ew, E);      // side 8

    // Join: seg1 needs both gemm1 (main) and reorder (side).
    cudaEventRecord(ev_join, s2);
    cudaStreamWaitEvent(0, ev_join, 0);

    seg_kernel<<<seg_blocks, 256>>>(b1, N, 0, 1);
    gemm_kernel<<<gemm_blocks, 256, GEMM_SMEM>>>(N, 1);
    seg_kernel<<<seg_blocks, 256>>>(b2, N, 1, 1);
    gemm_kernel<<<gemm_blocks, 256, GEMM_SMEM>>>(N, 2);
    seg_kernel<<<seg_blocks, 256>>>(b3, N, 2, 0);
    final_kernel<<<1, 128>>>(linW, linb, out);
}

// round 17
// speedup vs baseline: 2.0137x; 1.0232x over previous
#include <cuda_runtime.h>
#include <cuda_fp16.h>
#include <cuda_bf16.h>
#include <cstdint>

#define DF 128
#define NMAX 50000
#define EMAX 800000
#define NCLS 10
#define SCB 256
#define NSCB ((NMAX + 1 + SCB - 1) / SCB)

// Scratch (allocation-free __device__ globals).
__device__ __align__(16) __half g_support[(size_t)NMAX * DF];  // gemm out / seg in
__device__ __align__(16) __half g_ah[(size_t)NMAX * DF];       // fp16 activations (gemm A input)
__device__ __align__(16) __half g_w16[3 * DF * DF];            // fp16 weights
__device__ __align__(16) int2   g_edge_s[EMAX];
__device__ int g_cnt[NMAX + 1];
__device__ int g_rowptr[NMAX + 1];
__device__ int g_cur[NMAX + 1];
__device__ int g_blksum[NSCB];
__device__ int g_blkoff[NSCB];
__device__ unsigned g_okey[3 * DF];

__device__ __forceinline__ unsigned fenc(float x) {
    unsigned u = __float_as_uint(x);
    return (u & 0x80000000u) ? ~u : (u | 0x80000000u);
}
__device__ __forceinline__ float fdec(unsigned k) {
    unsigned u = (k & 0x80000000u) ? (k & 0x7FFFFFFFu) : ~k;
    return __uint_as_float(u);
}
__device__ __forceinline__ unsigned smem_u32(const void* p) {
    return (unsigned)__cvta_generic_to_shared(p);
}
__device__ __forceinline__ unsigned h2_as_u32(__half2 h) {
    return *reinterpret_cast<unsigned*>(&h);
}
#define CP_ASYNC16(sm, gp) \
    asm volatile("cp.async.cg.shared.global [%0], [%1], 16;" :: "r"(sm), "l"(gp))
#define CP_ASYNC_WAIT_ALL() \
    asm volatile("cp.async.commit_group;\ncp.async.wait_group 0;" ::: "memory")

// ---------------- prep: one-time fp32->fp16 conversion of x and W1/2/3 -----

__global__ __launch_bounds__(256) void prep_kernel(const float* __restrict__ x,
                                                   const float* __restrict__ W1,
                                                   const float* __restrict__ W2,
                                                   const float* __restrict__ W3,
                                                   int N) {
    long total = (long)N * 32;
    for (long i = (long)blockIdx.x * 256 + threadIdx.x; i < total;
         i += (long)gridDim.x * 256) {
        float4 v = ((const float4*)x)[i];
        uint2 pk;
        pk.x = h2_as_u32(__floats2half2_rn(v.x, v.y));
        pk.y = h2_as_u32(__floats2half2_rn(v.z, v.w));
        ((uint2*)g_ah)[i] = pk;
    }
    for (int i = blockIdx.x * 256 + threadIdx.x; i < 3 * DF * 32;
         i += gridDim.x * 256) {
        const float* Wsrc = (i < DF * 32) ? W1 : (i < 2 * DF * 32) ? W2 : W3;
        int li = i & (DF * 32 - 1);
        float4 v = ((const float4*)Wsrc)[li];
        uint2 pk;
        pk.x = h2_as_u32(__floats2half2_rn(v.x, v.y));
        pk.y = h2_as_u32(__floats2half2_rn(v.z, v.w));
        ((uint2*)g_w16)[i] = pk;
    }
}

// ---------------- sort: counting sort of edges by dst -------------------

__global__ __launch_bounds__(256) void init_kernel(int N) {
    int i = blockIdx.x * 256 + threadIdx.x;
    if (i <= N) g_cnt[i] = 0;
    if (i < 3 * DF) g_okey[i] = 0u;
}

__global__ __launch_bounds__(256) void hist_kernel(const int* __restrict__ dst, int E) {
    int e = blockIdx.x * 256 + threadIdx.x;
    if (e < E) atomicAdd(&g_cnt[dst[e]], 1);
}

__global__ __launch_bounds__(SCB) void scan1_kernel(int N) {
    __shared__ int sh[SCB];
    int t = threadIdx.x;
    int idx = blockIdx.x * SCB + t;
    int v = (idx < N) ? g_cnt[idx] : 0;
    sh[t] = v;
    __syncthreads();
    for (int off = SCB / 2; off > 0; off >>= 1) {
        if (t < off) sh[t] += sh[t + off];
        __syncthreads();
    }
    if (t == 0) g_blksum[blockIdx.x] = sh[0];
}

__global__ __launch_bounds__(SCB) void scan2_kernel() {
    __shared__ int sh[SCB];
    int t = threadIdx.x;
    sh[t] = (t < NSCB) ? g_blksum[t] : 0;
    __syncthreads();
    for (int off = 1; off < SCB; off <<= 1) {
        int v = sh[t];
        int add = (t >= off) ? sh[t - off] : 0;
        __syncthreads();
        sh[t] = v + add;
        __syncthreads();
    }
    if (t < NSCB) g_blkoff[t] = (t == 0) ? 0 : sh[t - 1];
}

__global__ __launch_bounds__(SCB) void scan3_kernel(int N) {
    __shared__ int sh[SCB];
    int t = threadIdx.x;
    int idx = blockIdx.x * SCB + t;
    int v = (idx < N) ? g_cnt[idx] : 0;
    sh[t] = v;
    __syncthreads();
    for (int off = 1; off < SCB; off <<= 1) {
        int x = sh[t];
        int add = (t >= off) ? sh[t - off] : 0;
        __syncthreads();
        sh[t] = x + add;
        __syncthreads();
    }
    if (idx <= N) {
        int excl = g_blkoff[blockIdx.x] + sh[t] - v;
        g_rowptr[idx] = excl;
        if (idx < N) g_cur[idx] = excl;
    }
}

__global__ __launch_bounds__(256) void reorder_kernel(const int* __restrict__ src,
                                                      const int* __restrict__ dst,
                                                      const float* __restrict__ w,
                                                      int E) {
    int e = blockIdx.x * 256 + threadIdx.x;
    if (e >= E) return;
    int d = dst[e];
    int pos = atomicAdd(&g_cur[d], 1);
    g_edge_s[pos] = make_int2(src[e], __float_as_int(w[e]));
}

// ---------------- GEMM: support(fp16) = g_ah(fp16) @ g_w16[layer] ----------
// Block tile 128(m) x 128(n); 8 warps 4(m)x2(n), warp tile 32x64.
// cp.async fp16 staging (no conversions). 2 CTAs/SM.

#define SH 136
#define GEMM_SMEM (2 * DF * SH * (int)sizeof(__half))  // 69632 B

__global__ __launch_bounds__(256, 2) void gemm_kernel(int N, int layer) {
    extern __shared__ __half smem_h[];
    __half* As = smem_h;             // [128 m][136] (k)
    __half* Ws = smem_h + DF * SH;   // [128 k][136] (n)

    int t = threadIdx.x;
    int lane = t & 31;
    int wrp = t >> 5;
    int wm = wrp >> 1;
    int wn = wrp & 1;
    int r0 = blockIdx.x * 128;

    const __half* Wg = g_w16 + layer * DF * DF;

    for (int i = t; i < DF * 16; i += 256) {
        int row = i >> 4;
        int sg = (i & 15) * 8;
        int gr = r0 + row;
        if (gr < N) {
            CP_ASYNC16(smem_u32(&As[row * SH + sg]), &g_ah[(size_t)gr * DF + sg]);
        } else {
            *(uint4*)&As[row * SH + sg] = make_uint4(0u, 0u, 0u, 0u);
        }
    }
    for (int i = t; i < DF * 16; i += 256) {
        int k = i >> 4;
        int sg = (i & 15) * 8;
        CP_ASYNC16(smem_u32(&Ws[k * SH + sg]), &Wg[k * DF + sg]);
    }
    CP_ASYNC_WAIT_ALL();
    __syncthreads();

    float acc[2][8][4];
#pragma unroll
    for (int mt = 0; mt < 2; mt++)
#pragma unroll
        for (int nt = 0; nt < 8; nt++)
#pragma unroll
            for (int r = 0; r < 4; r++) acc[mt][nt][r] = 0.f;

    int gid = lane >> 2;
    int tig = lane & 3;
    int tr = lane & 7;
    int tile = lane >> 3;
    int row_off = (tile & 1) ? 8 : 0;
    int col_off = (tile & 2) ? 8 : 0;

    unsigned addrA[2];
#pragma unroll
    for (int mt = 0; mt < 2; mt++) {
        int m0 = wm * 32 + mt * 16;
        addrA[mt] = smem_u32(&As[(m0 + tr + row_off) * SH + col_off]);
    }
    unsigned addrB[4];
#pragma unroll
    for (int np = 0; np < 4; np++) {
        int nb = wn * 64 + np * 16;
        addrB[np] = smem_u32(&Ws[(tr + row_off) * SH + nb + col_off]);
    }

#pragma unroll
    for (int ks = 0; ks < 8; ks++) {
        unsigned af[2][4];
#pragma unroll
        for (int mt = 0; mt < 2; mt++) {
            asm volatile(
                "ldmatrix.sync.aligned.m8n8.x4.shared.b16 {%0,%1,%2,%3}, [%4];"
                : "=r"(af[mt][0]), "=r"(af[mt][1]), "=r"(af[mt][2]), "=r"(af[mt][3])
                : "r"(addrA[mt] + ks * 16 * (unsigned)sizeof(__half)));
        }
        unsigned bf[4][4];
#pragma unroll
        for (int np = 0; np < 4; np++) {
            asm volatile(
                "ldmatrix.sync.aligned.m8n8.x4.trans.shared.b16 {%0,%1,%2,%3}, [%4];"
                : "=r"(bf[np][0]), "=r"(bf[np][1]), "=r"(bf[np][2]), "=r"(bf[np][3])
                : "r"(addrB[np] + ks * 16 * SH * (unsigned)sizeof(__half)));
        }
#pragma unroll
        for (int np = 0; np < 4; np++) {
#pragma unroll
            for (int sub = 0; sub < 2; sub++) {
                int nt = np * 2 + sub;
#pragma unroll
                for (int mt = 0; mt < 2; mt++) {
                    asm volatile(
                        "mma.sync.aligned.m16n8k16.row.col.f32.f16.f16.f32 "
                        "{%0,%1,%2,%3}, {%4,%5,%6,%7}, {%8,%9}, {%0,%1,%2,%3};"
                        : "+f"(acc[mt][nt][0]), "+f"(acc[mt][nt][1]),
                          "+f"(acc[mt][nt][2]), "+f"(acc[mt][nt][3])
                        : "r"(af[mt][0]), "r"(af[mt][1]),
                          "r"(af[mt][2]), "r"(af[mt][3]),
                        "r"(bf[np][sub * 2]), "r"(bf[np][sub * 2 + 1]));
                }
            }
        }
    }

#pragma unroll
    for (int mt = 0; mt < 2; mt++) {
#pragma unroll
        for (int nt = 0; nt < 8; nt++) {
            int row = r0 + wm * 32 + mt * 16 + gid;
            int col = wn * 64 + nt * 8 + 2 * tig;
            if (row < N)
                *(__half2*)&g_support[(size_t)row * DF + col] =
                    __floats2half2_rn(acc[mt][nt][0], acc[mt][nt][1]);
            if (row + 8 < N)
                *(__half2*)&g_support[(size_t)(row + 8) * DF + col] =
                    __floats2half2_rn(acc[mt][nt][2], acc[mt][nt][3]);
        }
    }
}

// ---------------- segment-sum + bias (+relu, fp16 h write) + column max ----
// TWO rows per warp over their contiguous merged edge range; per-edge
// accumulator steering via warp-uniform compare against the row split.

__device__ __forceinline__ void edge_fma(float4& a, const uint2 u, const float w) {
    float2 lo = __half22float2(*(const __half2*)&u.x);
    float2 hi = __half22float2(*(const __half2*)&u.y);
    a.x += lo.x * w; a.y += lo.y * w;
    a.z += hi.x * w; a.w += hi.y * w;
}

__global__ __launch_bounds__(256) void seg_kernel(const float* __restrict__ b,
                                                  int N, int layer, int do_relu) {
    __shared__ unsigned smax[DF];
    int t = threadIdx.x;
    int lane = t & 31;
    int wrp = t >> 5;
    if (t < DF) smax[t] = 0u;
    __syncthreads();

    int d0 = (blockIdx.x * 8 + wrp) * 2;
    if (d0 < N) {
        int d1 = d0 + 1;
        int beg = g_rowptr[d0];
        int split = g_rowptr[d1];            // d1 <= N always valid
        int end = (d1 < N) ? g_rowptr[d1 + 1] : split;
        const uint2* sup = (const uint2*)g_support;

        float4 acc0 = make_float4(0.f, 0.f, 0.f, 0.f);   // row d0
        float4 acc1 = make_float4(0.f, 0.f, 0.f, 0.f);   // row d1

        for (int base = beg; base < end; base += 32) {
            int m = end - base;
            if (m > 32) m = 32;
            int2 dsc = make_int2(0, 0);
            if (lane < m) dsc = g_edge_s[base + lane];

            int j = 0;
            for (; j + 8 <= m; j += 8) {
                int s0 = __shfl_sync(0xffffffffu, dsc.x, j + 0);
                int s1 = __shfl_sync(0xffffffffu, dsc.x, j + 1);
                int s2 = __shfl_sync(0xffffffffu, dsc.x, j + 2);
                int s3 = __shfl_sync(0xffffffffu, dsc.x, j + 3);
                int s4 = __shfl_sync(0xffffffffu, dsc.x, j + 4);
                int s5 = __shfl_sync(0xffffffffu, dsc.x, j + 5);
                int s6 = __shfl_sync(0xffffffffu, dsc.x, j + 6);
                int s7 = __shfl_sync(0xffffffffu, dsc.x, j + 7);
                float w0 = __int_as_float(__shfl_sync(0xffffffffu, dsc.y, j + 0));
                float w1 = __int_as_float(__shfl_sync(0xffffffffu, dsc.y, j + 1));
                float w2 = __int_as_float(__shfl_sync(0xffffffffu, dsc.y, j + 2));
                float w3 = __int_as_float(__shfl_sync(0xffffffffu, dsc.y, j + 3));
                float w4 = __int_as_float(__shfl_sync(0xffffffffu, dsc.y, j + 4));
                float w5 = __int_as_float(__shfl_sync(0xffffffffu, dsc.y, j + 5));
                float w6 = __int_as_float(__shfl_sync(0xffffffffu, dsc.y, j + 6));
                float w7 = __int_as_float(__shfl_sync(0xffffffffu, dsc.y, j + 7));
                uint2 u0 = sup[(size_t)s0 * 32 + lane];
                uint2 u1 = sup[(size_t)s1 * 32 + lane];
                uint2 u2 = sup[(size_t)s2 * 32 + lane];
                uint2 u3 = sup[(size_t)s3 * 32 + lane];
                uint2 u4 = sup[(size_t)s4 * 32 + lane];
                uint2 u5 = sup[(size_t)s5 * 32 + lane];
                uint2 u6 = sup[(size_t)s6 * 32 + lane];
                uint2 u7 = sup[(size_t)s7 * 32 + lane];
                // Warp-uniform steering: edge (base+j+q) belongs to d0 if < split.
                if (base + j + 0 < split) edge_fma(acc0, u0, w0); else edge_fma(acc1, u0, w0);
                if (base + j + 1 < split) edge_fma(acc0, u1, w1); else edge_fma(acc1, u1, w1);
                if (base + j + 2 < split) edge_fma(acc0, u2, w2); else edge_fma(acc1, u2, w2);
                if (base + j + 3 < split) edge_fma(acc0, u3, w3); else edge_fma(acc1, u3, w3);
                if (base + j + 4 < split) edge_fma(acc0, u4, w4); else edge_fma(acc1, u4, w4);
                if (base + j + 5 < split) edge_fma(acc0, u5, w5); else edge_fma(acc1, u5, w5);
                if (base + j + 6 < split) edge_fma(acc0, u6, w6); else edge_fma(acc1, u6, w6);
                if (base + j + 7 < split) edge_fma(acc0, u7, w7); else edge_fma(acc1, u7, w7);
            }
            for (; j < m; j++) {
                int s0 = __shfl_sync(0xffffffffu, dsc.x, j);
                float w0 = __int_as_float(__shfl_sync(0xffffffffu, dsc.y, j));
                uint2 u0 = sup[(size_t)s0 * 32 + lane];
                if (base + j < split) edge_fma(acc0, u0, w0);
                else edge_fma(acc1, u0, w0);
            }
        }

        const float4* bb = (const float4*)b;
        float4 bv = bb[lane];
        // Row d0
        {
            float4 v = make_float4(acc0.x + bv.x, acc0.y + bv.y,
                                   acc0.z + bv.z, acc0.w + bv.w);
            if (do_relu) {
                v.x = fmaxf(v.x, 0.f); v.y = fmaxf(v.y, 0.f);
                v.z = fmaxf(v.z, 0.f); v.w = fmaxf(v.w, 0.f);
                uint2 pk;
                pk.x = h2_as_u32(__floats2half2_rn(v.x, v.y));
                pk.y = h2_as_u32(__floats2half2_rn(v.z, v.w));
                *(uint2*)&g_ah[(size_t)d0 * DF + lane * 4] = pk;
            }
            atomicMax(&smax[lane * 4 + 0], fenc(v.x));
            atomicMax(&smax[lane * 4 + 1], fenc(v.y));
            atomicMax(&smax[lane * 4 + 2], fenc(v.z));
            atomicMax(&smax[lane * 4 + 3], fenc(v.w));
        }
        // Row d1
        if (d1 < N) {
            float4 v = make_float4(acc1.x + bv.x, acc1.y + bv.y,
                                   acc1.z + bv.z, acc1.w + bv.w);
            if (do_relu) {
                v.x = fmaxf(v.x, 0.f); v.y = fmaxf(v.y, 0.f);
                v.z = fmaxf(v.z, 0.f); v.w = fmaxf(v.w, 0.f);
                uint2 pk;
                pk.x = h2_as_u32(__floats2half2_rn(v.x, v.y));
                pk.y = h2_as_u32(__floats2half2_rn(v.z, v.w));
                *(uint2*)&g_ah[(size_t)d1 * DF + lane * 4] = pk;
            }
            atomicMax(&smax[lane * 4 + 0], fenc(v.x));
            atomicMax(&smax[lane * 4 + 1], fenc(v.y));
            atomicMax(&smax[lane * 4 + 2], fenc(v.z));
            atomicMax(&smax[lane * 4 + 3], fenc(v.w));
        }
    }
    __syncthreads();
    if (t < DF) atomicMax(&g_okey[layer * DF + t], smax[t]);
}

// ---------------- head ----------------------------------------------------

__global__ __launch_bounds__(128) void final_kernel(const float* __restrict__ lin_W,
                                                    const float* __restrict__ lin_b,
                                                    float* __restrict__ out) {
    __shared__ float lin_in[3 * DF];
    __shared__ float logits[NCLS];
    int t = threadIdx.x;
    for (int i = t; i < 3 * DF; i += 128) lin_in[i] = fdec(g_okey[i]);
    __syncthreads();
    if (t < NCLS) {
        float s = lin_b[t];
#pragma unroll 4
        for (int j = 0; j < 3 * DF; j++) s += lin_W[t * 3 * DF + j] * lin_in[j];
        logits[t] = s;
    }
    __syncthreads();
    if (t == 0) {
        float m = -3.402823466e+38f;
        for (int c = 0; c < NCLS; c++) m = fmaxf(m, logits[c]);
        float se = 0.f;
        for (int c = 0; c < NCLS; c++) se += expf(logits[c] - m);
        float lse = m + logf(se);
        for (int c = 0; c < NCLS; c++) out[c] = logits[c] - lse;
    }
}

extern "C" void kernel_launch(void* const* d_in, const int* in_sizes, int n_in,
                              void* d_out, int out_size) {
    const float* x    = (const float*)d_in[0];
    const int*   esrc = (const int*)d_in[1];
    const int*   edst = (const int*)d_in[2];
    const float* ew   = (const float*)d_in[3];
    const float* W1   = (const float*)d_in[4];
    const float* b1   = (const float*)d_in[5];
    const float* W2   = (const float*)d_in[6];
    const float* b2   = (const float*)d_in[7];
    const float* W3   = (const float*)d_in[8];
    const float* b3   = (const float*)d_in[9];
    const float* linW = (const float*)d_in[10];
    const float* linb = (const float*)d_in[11];
    float* out = (float*)d_out;

    int N = in_sizes[0] / DF;
    int E = in_sizes[1];

    static cudaStream_t s2;
    static cudaEvent_t ev_fork, ev_join;
    static int inited = 0;
    if (!inited) {
        cudaFuncSetAttribute(gemm_kernel, cudaFuncAttributeMaxDynamicSharedMemorySize, GEMM_SMEM);
        cudaStreamCreateWithFlags(&s2, cudaStreamNonBlocking);
        cudaEventCreateWithFlags(&ev_fork, cudaEventDisableTiming);
        cudaEventCreateWithFlags(&ev_join, cudaEventDisableTiming);
        inited = 1;
    }

    int eb = (E + 255) / 256;
    int gemm_blocks = (N + 127) / 128;
    int seg_blocks = (N + 15) / 16;
    int scan_blocks = (N + 1 + SCB - 1) / SCB;

    // Fork: sort chain on side stream, prep+gemm1 on main (capture) stream.
    cudaEventRecord(ev_fork, 0);
    cudaStreamWaitEvent(s2, ev_fork, 0);

    prep_kernel<<<2048, 256>>>(x, W1, W2, W3, N);               // main 1
    init_kernel<<<(N + 256) / 256, 256, 0, s2>>>(N);            // side 2
    hist_kernel<<<eb, 256, 0, s2>>>(edst, E);                   // side 3
    gemm_kernel<<<gemm_blocks, 256, GEMM_SMEM>>>(N, 0);         // main 4 <- capture slot
    scan1_kernel<<<scan_blocks, SCB, 0, s2>>>(N);               // side 5
    scan2_kernel<<<1, SCB, 0, s2>>>();                          // side 6
    scan3_kernel<<<scan_blocks, SCB, 0, s2>>>(N);               // side 7
    reorder_kernel<<<eb, 256, 0, s2>>>(esrc, edst, ew, E);      // side 8

    // Join: seg1 needs both gemm1 (main) and reorder (side).
    cudaEventRecord(ev_join, s2);
    cudaStreamWaitEvent(0, ev_join, 0);

    seg_kernel<<<seg_blocks, 256>>>(b1, N, 0, 1);
    gemm_kernel<<<gemm_blocks, 256, GEMM_SMEM>>>(N, 1);
    seg_kernel<<<seg_blocks, 256>>>(b2, N, 1, 1);
    gemm_kernel<<<gemm_blocks, 256, GEMM_SMEM>>>(N, 2);
    seg_kernel<<<seg_blocks, 256>>>(b3, N, 2, 0);
    final_kernel<<<1, 128>>>(linW, linb, out);
}